// round 1
// baseline (speedup 1.0000x reference)
#include <cuda_runtime.h>
#include <math.h>

#define NN 4096      // nodes
#define DIN 768
#define HID 512
#define DOUT 768
#define H 4
#define HCAT (H*HID) // 2048
#define ALPHA 0.2f
#define NEG_BIG -9e15f

// ---------------- scratch (__device__ globals; no allocations) ----------------
__device__ float g_Wh0[(long)H * NN * HID];      // 32 MB
__device__ float g_P[(long)H * NN * NN];         // 268 MB
__device__ float g_ssrc[H * NN];
__device__ float g_sdst[H * NN];
__device__ float g_Hcat[(long)NN * HCAT];        // raw concat of hp0
__device__ float g_R[(long)NN * HCAT];           // residual buffer (reused layer1, 768 cols)
__device__ float g_H1[(long)NN * HCAT];          // layer-0 output
__device__ float g_Wh1[(long)H * NN * DOUT];     // 48 MB
__device__ float g_HP1[(long)NN * DOUT];

// ---------------- generic fp32 tiled GEMM ----------------
// C[z][m][n] (ldc) = scale * sum_{kb} A[z*aB + kb*aKB + m*K + k] * B[z*bB + kb*bKB + k*N + n]  (+bias[n])
#define BM 128
#define BN 128
#define BK 8
#define TM 8
#define TN 8

__global__ __launch_bounds__(256)
void sgemm_kernel(const float* __restrict__ A, const float* __restrict__ B,
                  float* __restrict__ C,
                  int M, int N, int K,
                  long aBatch, long bBatch, long cBatch, int ldc,
                  int kBatch, long aKB, long bKB,
                  float scale, const float* __restrict__ bias)
{
    __shared__ float As[BK][BM];
    __shared__ float Bs[BK][BN];

    const int bz = blockIdx.z;
    const float* Ab = A + (long)bz * aBatch;
    const float* Bb = B + (long)bz * bBatch;
    float* Cb = C + (long)bz * cBatch;

    const int bm = blockIdx.y * BM;
    const int bn = blockIdx.x * BN;
    const int tid = threadIdx.x;

    const int arow = tid >> 1;          // 0..127
    const int acol = (tid & 1) * 4;     // 0 or 4
    const int brow = tid >> 5;          // 0..7
    const int bcol = (tid & 31) * 4;    // 0..124

    const int tm = (tid >> 4) * TM;
    const int tn = (tid & 15) * TN;

    float acc[TM][TN];
#pragma unroll
    for (int i = 0; i < TM; i++)
#pragma unroll
        for (int j = 0; j < TN; j++) acc[i][j] = 0.f;

    for (int kb = 0; kb < kBatch; ++kb) {
        const float* Ak = Ab + (long)kb * aKB;
        const float* Bk = Bb + (long)kb * bKB;
        for (int k0 = 0; k0 < K; k0 += BK) {
            float4 av = *(const float4*)(Ak + (long)(bm + arow) * K + k0 + acol);
            As[acol + 0][arow] = av.x;
            As[acol + 1][arow] = av.y;
            As[acol + 2][arow] = av.z;
            As[acol + 3][arow] = av.w;
            float4 bv = *(const float4*)(Bk + (long)(k0 + brow) * N + bn + bcol);
            *(float4*)&Bs[brow][bcol] = bv;
            __syncthreads();
#pragma unroll
            for (int k = 0; k < BK; ++k) {
                float ar[TM], br[TN];
                float4 a0 = *(const float4*)&As[k][tm];
                float4 a1 = *(const float4*)&As[k][tm + 4];
                ar[0]=a0.x; ar[1]=a0.y; ar[2]=a0.z; ar[3]=a0.w;
                ar[4]=a1.x; ar[5]=a1.y; ar[6]=a1.z; ar[7]=a1.w;
                float4 b0 = *(const float4*)&Bs[k][tn];
                float4 b1 = *(const float4*)&Bs[k][tn + 4];
                br[0]=b0.x; br[1]=b0.y; br[2]=b0.z; br[3]=b0.w;
                br[4]=b1.x; br[5]=b1.y; br[6]=b1.z; br[7]=b1.w;
#pragma unroll
                for (int i = 0; i < TM; i++)
#pragma unroll
                    for (int j = 0; j < TN; j++) acc[i][j] += ar[i] * br[j];
            }
            __syncthreads();
        }
    }

#pragma unroll
    for (int i = 0; i < TM; i++) {
        long rowoff = (long)(bm + tm + i) * ldc + bn + tn;
#pragma unroll
        for (int j = 0; j < TN; j++) {
            float v = acc[i][j] * scale;
            if (bias) v += bias[bn + tn + j];
            Cb[rowoff + j] = v;
        }
    }
}

// ---------------- scores: s = Wh . a  (src and dst halves) ----------------
__global__ void scores_kernel(const float* __restrict__ Wh, const float* __restrict__ a,
                              float* __restrict__ ssrc, float* __restrict__ sdst, int O)
{
    int warp = (blockIdx.x * blockDim.x + threadIdx.x) >> 5;
    int lane = threadIdx.x & 31;
    if (warp >= H * NN) return;
    int h = warp / NN;
    int n = warp % NN;
    const float* row = Wh + ((long)h * NN + n) * O;
    const float* a1 = a + (long)h * 2 * O;
    const float* a2 = a1 + O;
    float s1 = 0.f, s2 = 0.f;
    for (int o = lane; o < O; o += 32) {
        float v = row[o];
        s1 += v * a1[o];
        s2 += v * a2[o];
    }
#pragma unroll
    for (int off = 16; off > 0; off >>= 1) {
        s1 += __shfl_xor_sync(0xffffffffu, s1, off);
        s2 += __shfl_xor_sync(0xffffffffu, s2, off);
    }
    if (lane == 0) { ssrc[h * NN + n] = s1; sdst[h * NN + n] = s2; }
}

// ---------------- attention row softmax -> P ----------------
__global__ __launch_bounds__(256)
void attn_kernel(const int* __restrict__ adj, const float* __restrict__ ew,
                 const float* __restrict__ ssrc, const float* __restrict__ sdst,
                 float* __restrict__ P)
{
    __shared__ float sl[NN];
    __shared__ float red[8];
    const int i = blockIdx.x;
    const int h = blockIdx.y;
    const int tid = threadIdx.x;
    const float si = ssrc[h * NN + i];
    const float* sd = sdst + h * NN;
    const long rowbase = (long)i * NN;

    float lmax = -INFINITY;
    for (int j = tid; j < NN; j += 256) {
        int am = adj[rowbase + j];
        float w = ew[rowbase + j];
        bool m = (am > 0) || (j == i);
        float x = si + sd[j];
        float lr = x > 0.f ? x : ALPHA * x;
        float l = (m ? lr : NEG_BIG) * w;
        sl[j] = l;
        lmax = fmaxf(lmax, l);
    }
#pragma unroll
    for (int off = 16; off > 0; off >>= 1) lmax = fmaxf(lmax, __shfl_xor_sync(0xffffffffu, lmax, off));
    if ((tid & 31) == 0) red[tid >> 5] = lmax;
    __syncthreads();
    if (tid < 8) {
        float v = red[tid];
#pragma unroll
        for (int off = 4; off > 0; off >>= 1) v = fmaxf(v, __shfl_xor_sync(0xffu, v, off));
        if (tid == 0) red[0] = v;
    }
    __syncthreads();
    const float rowmax = red[0];
    __syncthreads();

    float lsum = 0.f;
    for (int j = tid; j < NN; j += 256) {
        float e = __expf(sl[j] - rowmax);
        sl[j] = e;
        lsum += e;
    }
#pragma unroll
    for (int off = 16; off > 0; off >>= 1) lsum += __shfl_xor_sync(0xffffffffu, lsum, off);
    if ((tid & 31) == 0) red[tid >> 5] = lsum;
    __syncthreads();
    if (tid < 8) {
        float v = red[tid];
#pragma unroll
        for (int off = 4; off > 0; off >>= 1) v += __shfl_xor_sync(0xffu, v, off);
        if (tid == 0) red[0] = v;
    }
    __syncthreads();
    const float inv = 1.f / red[0];

    float* prow = P + ((long)h * NN + i) * NN;
    for (int j = tid; j < NN; j += 256) prow[j] = sl[j] * inv;
}

// ---------------- layer-0 epilogue: H1 = elu(LN(elu(Hcat)+R)) ----------------
__global__ __launch_bounds__(256)
void fuse0_kernel(const float* __restrict__ Hcat, const float* __restrict__ R,
                  const float* __restrict__ g, const float* __restrict__ b,
                  float* __restrict__ H1)
{
    __shared__ float red[8];
    const int n = blockIdx.x;
    const int tid = threadIdx.x;
    float v[8];
    float sum = 0.f;
#pragma unroll
    for (int t = 0; t < 8; t++) {
        int c = tid + t * 256;
        float x = Hcat[(long)n * HCAT + c];
        x = x > 0.f ? x : (expf(x) - 1.f);      // elu on concat
        x += R[(long)n * HCAT + c];             // residual proj
        v[t] = x;
        sum += x;
    }
    // block sum -> mean
#pragma unroll
    for (int off = 16; off > 0; off >>= 1) sum += __shfl_xor_sync(0xffffffffu, sum, off);
    if ((tid & 31) == 0) red[tid >> 5] = sum;
    __syncthreads();
    if (tid < 8) {
        float x = red[tid];
#pragma unroll
        for (int off = 4; off > 0; off >>= 1) x += __shfl_xor_sync(0xffu, x, off);
        if (tid == 0) red[0] = x;
    }
    __syncthreads();
    const float mean = red[0] / HCAT;
    __syncthreads();
    float vs = 0.f;
#pragma unroll
    for (int t = 0; t < 8; t++) { float d = v[t] - mean; vs += d * d; }
#pragma unroll
    for (int off = 16; off > 0; off >>= 1) vs += __shfl_xor_sync(0xffffffffu, vs, off);
    if ((tid & 31) == 0) red[tid >> 5] = vs;
    __syncthreads();
    if (tid < 8) {
        float x = red[tid];
#pragma unroll
        for (int off = 4; off > 0; off >>= 1) x += __shfl_xor_sync(0xffu, x, off);
        if (tid == 0) red[0] = x;
    }
    __syncthreads();
    const float rstd = rsqrtf(red[0] / HCAT + 1e-5f);
#pragma unroll
    for (int t = 0; t < 8; t++) {
        int c = tid + t * 256;
        float y = (v[t] - mean) * rstd * g[c] + b[c];
        y = y > 0.f ? y : (expf(y) - 1.f);      // elu after LN
        H1[(long)n * HCAT + c] = y;
    }
}

// ---------------- final: out = LN(HP1 + R1) ----------------
__global__ __launch_bounds__(256)
void final_kernel(const float* __restrict__ HP1, const float* __restrict__ R,
                  const float* __restrict__ g, const float* __restrict__ b,
                  float* __restrict__ out)
{
    __shared__ float red[8];
    const int n = blockIdx.x;
    const int tid = threadIdx.x;
    float v[3];
    float sum = 0.f;
#pragma unroll
    for (int t = 0; t < 3; t++) {
        int c = tid + t * 256;
        float x = HP1[(long)n * DOUT + c] + R[(long)n * DOUT + c];
        v[t] = x;
        sum += x;
    }
#pragma unroll
    for (int off = 16; off > 0; off >>= 1) sum += __shfl_xor_sync(0xffffffffu, sum, off);
    if ((tid & 31) == 0) red[tid >> 5] = sum;
    __syncthreads();
    if (tid < 8) {
        float x = red[tid];
#pragma unroll
        for (int off = 4; off > 0; off >>= 1) x += __shfl_xor_sync(0xffu, x, off);
        if (tid == 0) red[0] = x;
    }
    __syncthreads();
    const float mean = red[0] / DOUT;
    __syncthreads();
    float vs = 0.f;
#pragma unroll
    for (int t = 0; t < 3; t++) { float d = v[t] - mean; vs += d * d; }
#pragma unroll
    for (int off = 16; off > 0; off >>= 1) vs += __shfl_xor_sync(0xffffffffu, vs, off);
    if ((tid & 31) == 0) red[tid >> 5] = vs;
    __syncthreads();
    if (tid < 8) {
        float x = red[tid];
#pragma unroll
        for (int off = 4; off > 0; off >>= 1) x += __shfl_xor_sync(0xffu, x, off);
        if (tid == 0) red[0] = x;
    }
    __syncthreads();
    const float rstd = rsqrtf(red[0] / DOUT + 1e-5f);
#pragma unroll
    for (int t = 0; t < 3; t++) {
        int c = tid + t * 256;
        out[(long)n * DOUT + c] = (v[t] - mean) * rstd * g[c] + b[c];
    }
}

// ---------------- host ----------------
extern "C" void kernel_launch(void* const* d_in, const int* in_sizes, int n_in,
                              void* d_out, int out_size)
{
    const float* X    = (const float*)d_in[0];
    const int*   adj  = (const int*)  d_in[1];
    const float* ew   = (const float*)d_in[2];
    const float* W0   = (const float*)d_in[3];
    const float* a0   = (const float*)d_in[4];
    const float* W1   = (const float*)d_in[5];
    const float* a1   = (const float*)d_in[6];
    const float* rp0w = (const float*)d_in[7];
    const float* rp0b = (const float*)d_in[8];
    const float* rp1w = (const float*)d_in[9];
    const float* rp1b = (const float*)d_in[10];
    const float* ln0g = (const float*)d_in[11];
    const float* ln0b = (const float*)d_in[12];
    const float* ln1g = (const float*)d_in[13];
    const float* ln1b = (const float*)d_in[14];
    float* out = (float*)d_out;

    float *Wh0, *P, *ssrc, *sdst, *Hcat, *R, *H1, *Wh1, *HP1;
    cudaGetSymbolAddress((void**)&Wh0,  g_Wh0);
    cudaGetSymbolAddress((void**)&P,    g_P);
    cudaGetSymbolAddress((void**)&ssrc, g_ssrc);
    cudaGetSymbolAddress((void**)&sdst, g_sdst);
    cudaGetSymbolAddress((void**)&Hcat, g_Hcat);
    cudaGetSymbolAddress((void**)&R,    g_R);
    cudaGetSymbolAddress((void**)&H1,   g_H1);
    cudaGetSymbolAddress((void**)&Wh1,  g_Wh1);
    cudaGetSymbolAddress((void**)&HP1,  g_HP1);

    dim3 blk(256);

    // ===== Layer 0 =====
    // Wh0[h] = X @ W0[h] : M=4096 N=512 K=768
    {
        dim3 grid(HID / BN, NN / BM, H);
        sgemm_kernel<<<grid, blk>>>(X, W0, Wh0, NN, HID, DIN,
                                    0L, (long)DIN * HID, (long)NN * HID, HID,
                                    1, 0L, 0L, 1.f, nullptr);
    }
    // scores
    scores_kernel<<<(H * NN) / 8, blk>>>(Wh0, a0, ssrc, sdst, HID);
    // attention softmax -> P
    {
        dim3 grid(NN, H);
        attn_kernel<<<grid, blk>>>(adj, ew, ssrc, sdst, P);
    }
    // Hcat[n, h*512+o] = P[h] @ Wh0[h] : M=4096 N=512 K=4096, ldc=2048, cBatch=512
    {
        dim3 grid(HID / BN, NN / BM, H);
        sgemm_kernel<<<grid, blk>>>(P, Wh0, Hcat, NN, HID, NN,
                                    (long)NN * NN, (long)NN * HID, (long)HID, HCAT,
                                    1, 0L, 0L, 1.f, nullptr);
    }
    // R = X @ rp0_w + rp0_b : M=4096 N=2048 K=768
    {
        dim3 grid(HCAT / BN, NN / BM, 1);
        sgemm_kernel<<<grid, blk>>>(X, rp0w, R, NN, HCAT, DIN,
                                    0L, 0L, 0L, HCAT,
                                    1, 0L, 0L, 1.f, rp0b);
    }
    // H1 = elu(LN(elu(Hcat) + R))
    fuse0_kernel<<<NN, blk>>>(Hcat, R, ln0g, ln0b, H1);

    // ===== Layer 1 =====
    // Wh1[h] = H1 @ W1[h] : M=4096 N=768 K=2048
    {
        dim3 grid(DOUT / BN, NN / BM, H);
        sgemm_kernel<<<grid, blk>>>(H1, W1, Wh1, NN, DOUT, HCAT,
                                    0L, (long)HCAT * DOUT, (long)NN * DOUT, DOUT,
                                    1, 0L, 0L, 1.f, nullptr);
    }
    // scores
    scores_kernel<<<(H * NN) / 8, blk>>>(Wh1, a1, ssrc, sdst, DOUT);
    // attention softmax -> P
    {
        dim3 grid(NN, H);
        attn_kernel<<<grid, blk>>>(adj, ew, ssrc, sdst, P);
    }
    // HP1 = 0.25 * sum_h P[h] @ Wh1[h] : M=4096 N=768 K=4096 x4 heads
    {
        dim3 grid(DOUT / BN, NN / BM, 1);
        sgemm_kernel<<<grid, blk>>>(P, Wh1, HP1, NN, DOUT, NN,
                                    0L, 0L, 0L, DOUT,
                                    H, (long)NN * NN, (long)NN * DOUT,
                                    0.25f, nullptr);
    }
    // R1 (reuse R, 768 cols) = H1 @ rp1_w + rp1_b : M=4096 N=768 K=2048
    {
        dim3 grid(DOUT / BN, NN / BM, 1);
        sgemm_kernel<<<grid, blk>>>(H1, rp1w, R, NN, DOUT, HCAT,
                                    0L, 0L, 0L, DOUT,
                                    1, 0L, 0L, 1.f, rp1b);
    }
    // out = LN(HP1 + R1)
    final_kernel<<<NN, blk>>>(HP1, R, ln1g, ln1b, out);
}

// round 3
// speedup vs baseline: 3.3019x; 3.3019x over previous
#include <cuda_runtime.h>
#include <math.h>
#include <stdint.h>

#define NN 4096      // nodes
#define DIN 768
#define HID 512
#define DOUT 768
#define H 4
#define HCAT (H*HID) // 2048
#define ALPHA 0.2f
#define NEG_BIG -9e15f

// ---------------- scratch (__device__ globals; no allocations) ----------------
__device__ float g_Wh0[(long)H * NN * HID];      // 32 MB
__device__ float g_P[(long)H * NN * NN];         // 268 MB
__device__ float g_ssrc[H * NN];
__device__ float g_sdst[H * NN];
__device__ float g_Hcat[(long)NN * HCAT];        // raw concat of hp0
__device__ float g_R[(long)NN * HCAT];           // residual buffer (reused layer1)
__device__ float g_H1[(long)NN * HCAT];          // layer-0 output
__device__ float g_Wh1[(long)H * NN * DOUT];     // 48 MB
__device__ float g_HP1[(long)NN * DOUT];

// ================= tf32 tensor-core GEMM =================
// C[z][m][n] (ldc) = scale * sum_{kb} A[z*aB + kb*aKB + m*K + k] * B[z*bB + kb*bKB + k*N + n] (+bias[n])
#define BM 128
#define BN 128
#define BK 32
#define LDA_S 36                    // padded A smem row (floats)
#define LDB_S 136                   // padded B smem row (floats)
#define A_STAGE (BM * LDA_S)        // 4608 floats
#define B_STAGE (BK * LDB_S)        // 4352 floats
#define STAGE_FLOATS (A_STAGE + B_STAGE)  // 8960
#define GEMM_SMEM_BYTES (2 * STAGE_FLOATS * 4)  // 71680 B

__device__ __forceinline__ uint32_t f2tf(float f) {
    uint32_t r;
    asm("cvt.rna.tf32.f32 %0, %1;" : "=r"(r) : "f"(f));
    return r;
}

__device__ __forceinline__ void cp16(uint32_t s, const float* g) {
    asm volatile("cp.async.cg.shared.global [%0], [%1], 16;\n" :: "r"(s), "l"(g));
}

__device__ __forceinline__ void mma_tf32(float* d, const uint32_t* a, const uint32_t* b) {
    asm volatile(
        "mma.sync.aligned.m16n8k8.row.col.f32.tf32.tf32.f32 "
        "{%0,%1,%2,%3}, {%4,%5,%6,%7}, {%8,%9}, {%0,%1,%2,%3};"
        : "+f"(d[0]), "+f"(d[1]), "+f"(d[2]), "+f"(d[3])
        : "r"(a[0]), "r"(a[1]), "r"(a[2]), "r"(a[3]), "r"(b[0]), "r"(b[1]));
}

__global__ __launch_bounds__(256)
void tgemm_kernel(const float* __restrict__ A, const float* __restrict__ B,
                  float* __restrict__ C,
                  int M, int N, int K,
                  long aBatch, long bBatch, long cBatch, int ldc,
                  int kBatch, long aKB, long bKB,
                  float scale, const float* __restrict__ bias)
{
    extern __shared__ float smem[];
    const int tid = threadIdx.x;
    const int w = tid >> 5, lane = tid & 31;
    const int wm = w >> 1, wn = w & 1;       // 4x2 warp grid
    const int g = lane >> 2, tg = lane & 3;  // groupID, thread-in-group

    const int bz = blockIdx.z;
    const float* Ab = A + (long)bz * aBatch;
    const float* Bb = B + (long)bz * bBatch;
    float* Cb = C + (long)bz * cBatch;
    const int bm = blockIdx.y * BM;
    const int bn = blockIdx.x * BN;

    float acc[2][8][4];
#pragma unroll
    for (int mi = 0; mi < 2; mi++)
#pragma unroll
        for (int ni = 0; ni < 8; ni++)
#pragma unroll
            for (int q = 0; q < 4; q++) acc[mi][ni][q] = 0.f;

    const int nk = K / BK;
    uint32_t smem_u32 = (uint32_t)__cvta_generic_to_shared(smem);

    // per-thread cp.async chunk coordinates (4 chunks A + 4 chunks B per stage)
    int ar[4], ac[4], br4[4], bc4[4];
#pragma unroll
    for (int i = 0; i < 4; i++) {
        int c = tid + i * 256;
        ar[i] = c >> 3;  ac[i] = (c & 7) * 4;    // A: 8 chunks per 32-float row
        br4[i] = c >> 5; bc4[i] = (c & 31) * 4;  // B: 32 chunks per 128-float row
    }

    for (int kb = 0; kb < kBatch; ++kb) {
        const float* Ak = Ab + (long)kb * aKB;
        const float* Bk = Bb + (long)kb * bKB;

        // prefetch stage 0
        {
            uint32_t abase = smem_u32;
            uint32_t bbase = smem_u32 + A_STAGE * 4;
#pragma unroll
            for (int i = 0; i < 4; i++) {
                cp16(abase + (ar[i] * LDA_S + ac[i]) * 4,
                     Ak + (long)(bm + ar[i]) * K + ac[i]);
                cp16(bbase + (br4[i] * LDB_S + bc4[i]) * 4,
                     Bk + (long)br4[i] * N + bn + bc4[i]);
            }
            asm volatile("cp.async.commit_group;\n");
        }

        for (int kt = 0; kt < nk; ++kt) {
            if (kt + 1 < nk) {
                int s = (kt + 1) & 1;
                uint32_t abase = smem_u32 + s * STAGE_FLOATS * 4;
                uint32_t bbase = abase + A_STAGE * 4;
                const long koff = (long)(kt + 1) * BK;
#pragma unroll
                for (int i = 0; i < 4; i++) {
                    cp16(abase + (ar[i] * LDA_S + ac[i]) * 4,
                         Ak + (long)(bm + ar[i]) * K + koff + ac[i]);
                    cp16(bbase + (br4[i] * LDB_S + bc4[i]) * 4,
                         Bk + (koff + br4[i]) * N + bn + bc4[i]);
                }
                asm volatile("cp.async.commit_group;\n");
                asm volatile("cp.async.wait_group 1;\n");
            } else {
                asm volatile("cp.async.wait_group 0;\n");
            }
            __syncthreads();

            const float* As = smem + (kt & 1) * STAGE_FLOATS;
            const float* Bs = As + A_STAGE;

#pragma unroll
            for (int k0 = 0; k0 < 4; k0++) {
                uint32_t afr[2][4];
#pragma unroll
                for (int mi = 0; mi < 2; mi++) {
                    int r = wm * 32 + mi * 16 + g;
                    int cidx = k0 * 8 + tg;
                    afr[mi][0] = f2tf(As[r * LDA_S + cidx]);
                    afr[mi][1] = f2tf(As[(r + 8) * LDA_S + cidx]);
                    afr[mi][2] = f2tf(As[r * LDA_S + cidx + 4]);
                    afr[mi][3] = f2tf(As[(r + 8) * LDA_S + cidx + 4]);
                }
                uint32_t bfr[8][2];
#pragma unroll
                for (int ni = 0; ni < 8; ni++) {
                    int col = wn * 64 + ni * 8 + g;
                    int row = k0 * 8 + tg;
                    bfr[ni][0] = f2tf(Bs[row * LDB_S + col]);
                    bfr[ni][1] = f2tf(Bs[(row + 4) * LDB_S + col]);
                }
#pragma unroll
                for (int mi = 0; mi < 2; mi++)
#pragma unroll
                    for (int ni = 0; ni < 8; ni++)
                        mma_tf32(acc[mi][ni], afr[mi], bfr[ni]);
            }
            __syncthreads();
        }
    }

    // epilogue
#pragma unroll
    for (int mi = 0; mi < 2; mi++) {
        int r0 = bm + wm * 32 + mi * 16 + g;
#pragma unroll
        for (int ni = 0; ni < 8; ni++) {
            int c0 = bn + wn * 64 + ni * 8 + 2 * tg;
            float b0 = bias ? bias[c0] : 0.f;
            float b1 = bias ? bias[c0 + 1] : 0.f;
            float2 v01 = make_float2(acc[mi][ni][0] * scale + b0,
                                     acc[mi][ni][1] * scale + b1);
            float2 v23 = make_float2(acc[mi][ni][2] * scale + b0,
                                     acc[mi][ni][3] * scale + b1);
            *(float2*)&Cb[(long)r0 * ldc + c0] = v01;
            *(float2*)&Cb[(long)(r0 + 8) * ldc + c0] = v23;
        }
    }
}

// ---------------- scores: s = Wh . a  (src and dst halves) ----------------
__global__ void scores_kernel(const float* __restrict__ Wh, const float* __restrict__ a,
                              float* __restrict__ ssrc, float* __restrict__ sdst, int O)
{
    int warp = (blockIdx.x * blockDim.x + threadIdx.x) >> 5;
    int lane = threadIdx.x & 31;
    if (warp >= H * NN) return;
    int h = warp / NN;
    int n = warp % NN;
    const float* row = Wh + ((long)h * NN + n) * O;
    const float* a1 = a + (long)h * 2 * O;
    const float* a2 = a1 + O;
    float s1 = 0.f, s2 = 0.f;
    for (int o = lane; o < O; o += 32) {
        float v = row[o];
        s1 += v * a1[o];
        s2 += v * a2[o];
    }
#pragma unroll
    for (int off = 16; off > 0; off >>= 1) {
        s1 += __shfl_xor_sync(0xffffffffu, s1, off);
        s2 += __shfl_xor_sync(0xffffffffu, s2, off);
    }
    if (lane == 0) { ssrc[h * NN + n] = s1; sdst[h * NN + n] = s2; }
}

// ---------------- attention row softmax -> P ----------------
__global__ __launch_bounds__(256)
void attn_kernel(const int* __restrict__ adj, const float* __restrict__ ew,
                 const float* __restrict__ ssrc, const float* __restrict__ sdst,
                 float* __restrict__ P)
{
    __shared__ float sl[NN];
    __shared__ float red[8];
    const int i = blockIdx.x;
    const int h = blockIdx.y;
    const int tid = threadIdx.x;
    const float si = ssrc[h * NN + i];
    const float* sd = sdst + h * NN;
    const long rowbase = (long)i * NN;

    float lmax = -INFINITY;
    for (int j = tid; j < NN; j += 256) {
        int am = adj[rowbase + j];
        float w = ew[rowbase + j];
        bool m = (am > 0) || (j == i);
        float x = si + sd[j];
        float lr = x > 0.f ? x : ALPHA * x;
        float l = (m ? lr : NEG_BIG) * w;
        sl[j] = l;
        lmax = fmaxf(lmax, l);
    }
#pragma unroll
    for (int off = 16; off > 0; off >>= 1) lmax = fmaxf(lmax, __shfl_xor_sync(0xffffffffu, lmax, off));
    if ((tid & 31) == 0) red[tid >> 5] = lmax;
    __syncthreads();
    if (tid < 8) {
        float v = red[tid];
#pragma unroll
        for (int off = 4; off > 0; off >>= 1) v = fmaxf(v, __shfl_xor_sync(0xffu, v, off));
        if (tid == 0) red[0] = v;
    }
    __syncthreads();
    const float rowmax = red[0];
    __syncthreads();

    float lsum = 0.f;
    for (int j = tid; j < NN; j += 256) {
        float e = __expf(sl[j] - rowmax);
        sl[j] = e;
        lsum += e;
    }
#pragma unroll
    for (int off = 16; off > 0; off >>= 1) lsum += __shfl_xor_sync(0xffffffffu, lsum, off);
    if ((tid & 31) == 0) red[tid >> 5] = lsum;
    __syncthreads();
    if (tid < 8) {
        float v = red[tid];
#pragma unroll
        for (int off = 4; off > 0; off >>= 1) v += __shfl_xor_sync(0xffu, v, off);
        if (tid == 0) red[0] = v;
    }
    __syncthreads();
    const float inv = 1.f / red[0];

    float* prow = P + ((long)h * NN + i) * NN;
    for (int j = tid; j < NN; j += 256) prow[j] = sl[j] * inv;
}

// ---------------- layer-0 epilogue: H1 = elu(LN(elu(Hcat)+R)) ----------------
__global__ __launch_bounds__(256)
void fuse0_kernel(const float* __restrict__ Hcat, const float* __restrict__ R,
                  const float* __restrict__ g, const float* __restrict__ b,
                  float* __restrict__ H1)
{
    __shared__ float red[8];
    const int n = blockIdx.x;
    const int tid = threadIdx.x;
    float v[8];
    float sum = 0.f;
#pragma unroll
    for (int t = 0; t < 8; t++) {
        int c = tid + t * 256;
        float x = Hcat[(long)n * HCAT + c];
        x = x > 0.f ? x : (expf(x) - 1.f);      // elu on concat
        x += R[(long)n * HCAT + c];             // residual proj
        v[t] = x;
        sum += x;
    }
#pragma unroll
    for (int off = 16; off > 0; off >>= 1) sum += __shfl_xor_sync(0xffffffffu, sum, off);
    if ((tid & 31) == 0) red[tid >> 5] = sum;
    __syncthreads();
    if (tid < 8) {
        float x = red[tid];
#pragma unroll
        for (int off = 4; off > 0; off >>= 1) x += __shfl_xor_sync(0xffu, x, off);
        if (tid == 0) red[0] = x;
    }
    __syncthreads();
    const float mean = red[0] / HCAT;
    __syncthreads();
    float vs = 0.f;
#pragma unroll
    for (int t = 0; t < 8; t++) { float d = v[t] - mean; vs += d * d; }
#pragma unroll
    for (int off = 16; off > 0; off >>= 1) vs += __shfl_xor_sync(0xffffffffu, vs, off);
    if ((tid & 31) == 0) red[tid >> 5] = vs;
    __syncthreads();
    if (tid < 8) {
        float x = red[tid];
#pragma unroll
        for (int off = 4; off > 0; off >>= 1) x += __shfl_xor_sync(0xffu, x, off);
        if (tid == 0) red[0] = x;
    }
    __syncthreads();
    const float rstd = rsqrtf(red[0] / HCAT + 1e-5f);
#pragma unroll
    for (int t = 0; t < 8; t++) {
        int c = tid + t * 256;
        float y = (v[t] - mean) * rstd * g[c] + b[c];
        y = y > 0.f ? y : (expf(y) - 1.f);      // elu after LN
        H1[(long)n * HCAT + c] = y;
    }
}

// ---------------- final: out = LN(HP1 + R1) ----------------
__global__ __launch_bounds__(256)
void final_kernel(const float* __restrict__ HP1, const float* __restrict__ R,
                  const float* __restrict__ g, const float* __restrict__ b,
                  float* __restrict__ out)
{
    __shared__ float red[8];
    const int n = blockIdx.x;
    const int tid = threadIdx.x;
    float v[3];
    float sum = 0.f;
#pragma unroll
    for (int t = 0; t < 3; t++) {
        int c = tid + t * 256;
        float x = HP1[(long)n * DOUT + c] + R[(long)n * DOUT + c];
        v[t] = x;
        sum += x;
    }
#pragma unroll
    for (int off = 16; off > 0; off >>= 1) sum += __shfl_xor_sync(0xffffffffu, sum, off);
    if ((tid & 31) == 0) red[tid >> 5] = sum;
    __syncthreads();
    if (tid < 8) {
        float x = red[tid];
#pragma unroll
        for (int off = 4; off > 0; off >>= 1) x += __shfl_xor_sync(0xffu, x, off);
        if (tid == 0) red[0] = x;
    }
    __syncthreads();
    const float mean = red[0] / DOUT;
    __syncthreads();
    float vs = 0.f;
#pragma unroll
    for (int t = 0; t < 3; t++) { float d = v[t] - mean; vs += d * d; }
#pragma unroll
    for (int off = 16; off > 0; off >>= 1) vs += __shfl_xor_sync(0xffffffffu, vs, off);
    if ((tid & 31) == 0) red[tid >> 5] = vs;
    __syncthreads();
    if (tid < 8) {
        float x = red[tid];
#pragma unroll
        for (int off = 4; off > 0; off >>= 1) x += __shfl_xor_sync(0xffu, x, off);
        if (tid == 0) red[0] = x;
    }
    __syncthreads();
    const float rstd = rsqrtf(red[0] / DOUT + 1e-5f);
#pragma unroll
    for (int t = 0; t < 3; t++) {
        int c = tid + t * 256;
        out[(long)n * DOUT + c] = (v[t] - mean) * rstd * g[c] + b[c];
    }
}

// ---------------- host ----------------
extern "C" void kernel_launch(void* const* d_in, const int* in_sizes, int n_in,
                              void* d_out, int out_size)
{
    const float* X    = (const float*)d_in[0];
    const int*   adj  = (const int*)  d_in[1];
    const float* ew   = (const float*)d_in[2];
    const float* W0   = (const float*)d_in[3];
    const float* a0   = (const float*)d_in[4];
    const float* W1   = (const float*)d_in[5];
    const float* a1   = (const float*)d_in[6];
    const float* rp0w = (const float*)d_in[7];
    const float* rp0b = (const float*)d_in[8];
    const float* rp1w = (const float*)d_in[9];
    const float* rp1b = (const float*)d_in[10];
    const float* ln0g = (const float*)d_in[11];
    const float* ln0b = (const float*)d_in[12];
    const float* ln1g = (const float*)d_in[13];
    const float* ln1b = (const float*)d_in[14];
    float* out = (float*)d_out;

    float *Wh0, *P, *ssrc, *sdst, *Hcat, *R, *H1, *Wh1, *HP1;
    cudaGetSymbolAddress((void**)&Wh0,  g_Wh0);
    cudaGetSymbolAddress((void**)&P,    g_P);
    cudaGetSymbolAddress((void**)&ssrc, g_ssrc);
    cudaGetSymbolAddress((void**)&sdst, g_sdst);
    cudaGetSymbolAddress((void**)&Hcat, g_Hcat);
    cudaGetSymbolAddress((void**)&R,    g_R);
    cudaGetSymbolAddress((void**)&H1,   g_H1);
    cudaGetSymbolAddress((void**)&Wh1,  g_Wh1);
    cudaGetSymbolAddress((void**)&HP1,  g_HP1);

    cudaFuncSetAttribute(tgemm_kernel, cudaFuncAttributeMaxDynamicSharedMemorySize,
                         GEMM_SMEM_BYTES);

    dim3 blk(256);

    // ===== Layer 0 =====
    // Wh0[h] = X @ W0[h] : M=4096 N=512 K=768
    {
        dim3 grid(HID / BN, NN / BM, H);
        tgemm_kernel<<<grid, blk, GEMM_SMEM_BYTES>>>(X, W0, Wh0, NN, HID, DIN,
                                    0L, (long)DIN * HID, (long)NN * HID, HID,
                                    1, 0L, 0L, 1.f, nullptr);
    }
    scores_kernel<<<(H * NN) / 8, blk>>>(Wh0, a0, ssrc, sdst, HID);
    {
        dim3 grid(NN, H);
        attn_kernel<<<grid, blk>>>(adj, ew, ssrc, sdst, P);
    }
    // Hcat[n, h*512+o] = P[h] @ Wh0[h] : M=4096 N=512 K=4096, ldc=2048
    {
        dim3 grid(HID / BN, NN / BM, H);
        tgemm_kernel<<<grid, blk, GEMM_SMEM_BYTES>>>(P, Wh0, Hcat, NN, HID, NN,
                                    (long)NN * NN, (long)NN * HID, (long)HID, HCAT,
                                    1, 0L, 0L, 1.f, nullptr);
    }
    // R = X @ rp0_w + rp0_b : M=4096 N=2048 K=768
    {
        dim3 grid(HCAT / BN, NN / BM, 1);
        tgemm_kernel<<<grid, blk, GEMM_SMEM_BYTES>>>(X, rp0w, R, NN, HCAT, DIN,
                                    0L, 0L, 0L, HCAT,
                                    1, 0L, 0L, 1.f, rp0b);
    }
    fuse0_kernel<<<NN, blk>>>(Hcat, R, ln0g, ln0b, H1);

    // ===== Layer 1 =====
    // Wh1[h] = H1 @ W1[h] : M=4096 N=768 K=2048
    {
        dim3 grid(DOUT / BN, NN / BM, H);
        tgemm_kernel<<<grid, blk, GEMM_SMEM_BYTES>>>(H1, W1, Wh1, NN, DOUT, HCAT,
                                    0L, (long)HCAT * DOUT, (long)NN * DOUT, DOUT,
                                    1, 0L, 0L, 1.f, nullptr);
    }
    scores_kernel<<<(H * NN) / 8, blk>>>(Wh1, a1, ssrc, sdst, DOUT);
    {
        dim3 grid(NN, H);
        attn_kernel<<<grid, blk>>>(adj, ew, ssrc, sdst, P);
    }
    // HP1 = 0.25 * sum_h P[h] @ Wh1[h] : M=4096 N=768 K=4096 x4 heads
    {
        dim3 grid(DOUT / BN, NN / BM, 1);
        tgemm_kernel<<<grid, blk, GEMM_SMEM_BYTES>>>(P, Wh1, HP1, NN, DOUT, NN,
                                    0L, 0L, 0L, DOUT,
                                    H, (long)NN * NN, (long)NN * DOUT,
                                    0.25f, nullptr);
    }
    // R1 = H1 @ rp1_w + rp1_b : M=4096 N=768 K=2048
    {
        dim3 grid(DOUT / BN, NN / BM, 1);
        tgemm_kernel<<<grid, blk, GEMM_SMEM_BYTES>>>(H1, rp1w, R, NN, DOUT, HCAT,
                                    0L, 0L, 0L, DOUT,
                                    1, 0L, 0L, 1.f, rp1b);
    }
    final_kernel<<<NN, blk>>>(HP1, R, ln1g, ln1b, out);
}

// round 4
// speedup vs baseline: 3.6071x; 1.0924x over previous
#include <cuda_runtime.h>
#include <math.h>
#include <stdint.h>

#define NN 4096      // nodes
#define DIN 768
#define HID 512
#define DOUT 768
#define H 4
#define HCAT (H*HID) // 2048
#define ALPHA 0.2f
#define NEG_BIG -9e15f

// ---------------- scratch (__device__ globals; no allocations) ----------------
__device__ float g_Wh0[(long)H * NN * HID];      // 32 MB
__device__ float g_P[(long)H * NN * NN];         // 268 MB
__device__ float g_ssrc[H * NN];
__device__ float g_sdst[H * NN];
__device__ float g_Hcat[(long)NN * HCAT];        // raw concat of hp0
__device__ float g_R[(long)NN * HCAT];           // residual buffer (reused layer1)
__device__ float g_H1[(long)NN * HCAT];          // layer-0 output
__device__ float g_Wh1[(long)H * NN * DOUT];     // 48 MB
__device__ float g_HP1h[(long)H * NN * DOUT];    // per-head HP1 slices, 48 MB

// ================= tf32 tensor-core GEMM (3-stage cp.async) =================
// C[z][m][n] (ldc) = scale * A[z*aB + m*K + k] * B[z*bB + k*N + n] (+bias[n])
#define BM 128
#define BN 128
#define BK 32
#define NSTAGE 3
#define LDA_S 36                    // padded A smem row (floats)
#define LDB_S 136                   // padded B smem row (floats)
#define A_STAGE (BM * LDA_S)        // 4608 floats
#define B_STAGE (BK * LDB_S)        // 4352 floats
#define STAGE_FLOATS (A_STAGE + B_STAGE)  // 8960
#define GEMM_SMEM_BYTES (NSTAGE * STAGE_FLOATS * 4)  // 107520 B

__device__ __forceinline__ uint32_t f2tf(float f) {
    uint32_t r;
    asm("cvt.rna.tf32.f32 %0, %1;" : "=r"(r) : "f"(f));
    return r;
}

__device__ __forceinline__ void cp16(uint32_t s, const float* g) {
    asm volatile("cp.async.cg.shared.global [%0], [%1], 16;\n" :: "r"(s), "l"(g));
}

__device__ __forceinline__ void mma_tf32(float* d, const uint32_t* a, const uint32_t* b) {
    asm volatile(
        "mma.sync.aligned.m16n8k8.row.col.f32.tf32.tf32.f32 "
        "{%0,%1,%2,%3}, {%4,%5,%6,%7}, {%8,%9}, {%0,%1,%2,%3};"
        : "+f"(d[0]), "+f"(d[1]), "+f"(d[2]), "+f"(d[3])
        : "r"(a[0]), "r"(a[1]), "r"(a[2]), "r"(a[3]), "r"(b[0]), "r"(b[1]));
}

__global__ __launch_bounds__(256)
void tgemm_kernel(const float* __restrict__ A, const float* __restrict__ B,
                  float* __restrict__ C,
                  int N, int K,
                  long aBatch, long bBatch, long cBatch, int ldc,
                  float scale, const float* __restrict__ bias)
{
    extern __shared__ float smem[];
    const int tid = threadIdx.x;
    const int w = tid >> 5, lane = tid & 31;
    const int wm = w >> 1, wn = w & 1;       // 4x2 warp grid
    const int g = lane >> 2, tg = lane & 3;  // groupID, thread-in-group

    const int bz = blockIdx.z;
    const float* Ab = A + (long)bz * aBatch;
    const float* Bb = B + (long)bz * bBatch;
    float* Cb = C + (long)bz * cBatch;
    const int bm = blockIdx.y * BM;
    const int bn = blockIdx.x * BN;

    float acc[2][8][4];
#pragma unroll
    for (int mi = 0; mi < 2; mi++)
#pragma unroll
        for (int ni = 0; ni < 8; ni++)
#pragma unroll
            for (int q = 0; q < 4; q++) acc[mi][ni][q] = 0.f;

    const int nk = K / BK;
    uint32_t smem_u32 = (uint32_t)__cvta_generic_to_shared(smem);

    // per-thread cp.async chunk coordinates (4 chunks A + 4 chunks B per stage)
    int ar[4], ac[4], br4[4], bc4[4];
#pragma unroll
    for (int i = 0; i < 4; i++) {
        int c = tid + i * 256;
        ar[i] = c >> 3;  ac[i] = (c & 7) * 4;    // A: 8 chunks per 32-float row
        br4[i] = c >> 5; bc4[i] = (c & 31) * 4;  // B: 32 chunks per 128-float row
    }

    // prefetch stages 0 and 1
#pragma unroll
    for (int s = 0; s < 2; s++) {
        uint32_t abase = smem_u32 + s * STAGE_FLOATS * 4;
        uint32_t bbase = abase + A_STAGE * 4;
        const long koff = (long)s * BK;
#pragma unroll
        for (int i = 0; i < 4; i++) {
            cp16(abase + (ar[i] * LDA_S + ac[i]) * 4,
                 Ab + (long)(bm + ar[i]) * K + koff + ac[i]);
            cp16(bbase + (br4[i] * LDB_S + bc4[i]) * 4,
                 Bb + (koff + br4[i]) * N + bn + bc4[i]);
        }
        asm volatile("cp.async.commit_group;\n");
    }

    for (int kt = 0; kt < nk; ++kt) {
        if (kt + 1 < nk) asm volatile("cp.async.wait_group 1;\n");
        else             asm volatile("cp.async.wait_group 0;\n");
        __syncthreads();

        const float* As = smem + (kt % NSTAGE) * STAGE_FLOATS;
        const float* Bs = As + A_STAGE;

#pragma unroll
        for (int k0 = 0; k0 < 4; k0++) {
            uint32_t afr[2][4];
#pragma unroll
            for (int mi = 0; mi < 2; mi++) {
                int r = wm * 32 + mi * 16 + g;
                int cidx = k0 * 8 + tg;
                afr[mi][0] = f2tf(As[r * LDA_S + cidx]);
                afr[mi][1] = f2tf(As[(r + 8) * LDA_S + cidx]);
                afr[mi][2] = f2tf(As[r * LDA_S + cidx + 4]);
                afr[mi][3] = f2tf(As[(r + 8) * LDA_S + cidx + 4]);
            }
            uint32_t bfr[8][2];
#pragma unroll
            for (int ni = 0; ni < 8; ni++) {
                int col = wn * 64 + ni * 8 + g;
                int row = k0 * 8 + tg;
                bfr[ni][0] = f2tf(Bs[row * LDB_S + col]);
                bfr[ni][1] = f2tf(Bs[(row + 4) * LDB_S + col]);
            }
#pragma unroll
            for (int mi = 0; mi < 2; mi++)
#pragma unroll
                for (int ni = 0; ni < 8; ni++)
                    mma_tf32(acc[mi][ni], afr[mi], bfr[ni]);
        }

        // prefetch stage kt+2 (overwrites stage consumed at kt-1; safe after the
        // barrier above, which ordered all threads past that compute)
        if (kt + 2 < nk) {
            int s = (kt + 2) % NSTAGE;
            uint32_t abase = smem_u32 + s * STAGE_FLOATS * 4;
            uint32_t bbase = abase + A_STAGE * 4;
            const long koff = (long)(kt + 2) * BK;
#pragma unroll
            for (int i = 0; i < 4; i++) {
                cp16(abase + (ar[i] * LDA_S + ac[i]) * 4,
                     Ab + (long)(bm + ar[i]) * K + koff + ac[i]);
                cp16(bbase + (br4[i] * LDB_S + bc4[i]) * 4,
                     Bb + (koff + br4[i]) * N + bn + bc4[i]);
            }
            asm volatile("cp.async.commit_group;\n");
        } else {
            // keep group accounting uniform (empty group)
            asm volatile("cp.async.commit_group;\n");
        }
    }

    // epilogue
#pragma unroll
    for (int mi = 0; mi < 2; mi++) {
        int r0 = bm + wm * 32 + mi * 16 + g;
#pragma unroll
        for (int ni = 0; ni < 8; ni++) {
            int c0 = bn + wn * 64 + ni * 8 + 2 * tg;
            float b0 = bias ? bias[c0] : 0.f;
            float b1 = bias ? bias[c0 + 1] : 0.f;
            float2 v01 = make_float2(acc[mi][ni][0] * scale + b0,
                                     acc[mi][ni][1] * scale + b1);
            float2 v23 = make_float2(acc[mi][ni][2] * scale + b0,
                                     acc[mi][ni][3] * scale + b1);
            *(float2*)&Cb[(long)r0 * ldc + c0] = v01;
            *(float2*)&Cb[(long)(r0 + 8) * ldc + c0] = v23;
        }
    }
}

// ---------------- scores: s = Wh . a  (src and dst halves) ----------------
__global__ void scores_kernel(const float* __restrict__ Wh, const float* __restrict__ a,
                              float* __restrict__ ssrc, float* __restrict__ sdst, int O)
{
    int warp = (blockIdx.x * blockDim.x + threadIdx.x) >> 5;
    int lane = threadIdx.x & 31;
    if (warp >= H * NN) return;
    int h = warp / NN;
    int n = warp % NN;
    const float* row = Wh + ((long)h * NN + n) * O;
    const float* a1 = a + (long)h * 2 * O;
    const float* a2 = a1 + O;
    float s1 = 0.f, s2 = 0.f;
    for (int o = lane; o < O; o += 32) {
        float v = row[o];
        s1 += v * a1[o];
        s2 += v * a2[o];
    }
#pragma unroll
    for (int off = 16; off > 0; off >>= 1) {
        s1 += __shfl_xor_sync(0xffffffffu, s1, off);
        s2 += __shfl_xor_sync(0xffffffffu, s2, off);
    }
    if (lane == 0) { ssrc[h * NN + n] = s1; sdst[h * NN + n] = s2; }
}

// ---------------- attention row softmax -> P ----------------
__global__ __launch_bounds__(256)
void attn_kernel(const int* __restrict__ adj, const float* __restrict__ ew,
                 const float* __restrict__ ssrc, const float* __restrict__ sdst,
                 float* __restrict__ P)
{
    __shared__ float sl[NN];
    __shared__ float red[8];
    const int i = blockIdx.x;
    const int h = blockIdx.y;
    const int tid = threadIdx.x;
    const float si = ssrc[h * NN + i];
    const float* sd = sdst + h * NN;
    const long rowbase = (long)i * NN;

    float lmax = -INFINITY;
    for (int j = tid; j < NN; j += 256) {
        int am = adj[rowbase + j];
        float w = ew[rowbase + j];
        bool m = (am > 0) || (j == i);
        float x = si + sd[j];
        float lr = x > 0.f ? x : ALPHA * x;
        float l = (m ? lr : NEG_BIG) * w;
        sl[j] = l;
        lmax = fmaxf(lmax, l);
    }
#pragma unroll
    for (int off = 16; off > 0; off >>= 1) lmax = fmaxf(lmax, __shfl_xor_sync(0xffffffffu, lmax, off));
    if ((tid & 31) == 0) red[tid >> 5] = lmax;
    __syncthreads();
    if (tid < 8) {
        float v = red[tid];
#pragma unroll
        for (int off = 4; off > 0; off >>= 1) v = fmaxf(v, __shfl_xor_sync(0xffu, v, off));
        if (tid == 0) red[0] = v;
    }
    __syncthreads();
    const float rowmax = red[0];
    __syncthreads();

    float lsum = 0.f;
    for (int j = tid; j < NN; j += 256) {
        float e = __expf(sl[j] - rowmax);
        sl[j] = e;
        lsum += e;
    }
#pragma unroll
    for (int off = 16; off > 0; off >>= 1) lsum += __shfl_xor_sync(0xffffffffu, lsum, off);
    if ((tid & 31) == 0) red[tid >> 5] = lsum;
    __syncthreads();
    if (tid < 8) {
        float v = red[tid];
#pragma unroll
        for (int off = 4; off > 0; off >>= 1) v += __shfl_xor_sync(0xffu, v, off);
        if (tid == 0) red[0] = v;
    }
    __syncthreads();
    const float inv = 1.f / red[0];

    float* prow = P + ((long)h * NN + i) * NN;
    for (int j = tid; j < NN; j += 256) prow[j] = sl[j] * inv;
}

// ---------------- layer-0 epilogue: H1 = elu(LN(elu(Hcat)+R)) ----------------
__global__ __launch_bounds__(256)
void fuse0_kernel(const float* __restrict__ Hcat, const float* __restrict__ R,
                  const float* __restrict__ g, const float* __restrict__ b,
                  float* __restrict__ H1)
{
    __shared__ float red[8];
    const int n = blockIdx.x;
    const int tid = threadIdx.x;
    float v[8];
    float sum = 0.f;
#pragma unroll
    for (int t = 0; t < 8; t++) {
        int c = tid + t * 256;
        float x = Hcat[(long)n * HCAT + c];
        x = x > 0.f ? x : (expf(x) - 1.f);      // elu on concat
        x += R[(long)n * HCAT + c];             // residual proj
        v[t] = x;
        sum += x;
    }
#pragma unroll
    for (int off = 16; off > 0; off >>= 1) sum += __shfl_xor_sync(0xffffffffu, sum, off);
    if ((tid & 31) == 0) red[tid >> 5] = sum;
    __syncthreads();
    if (tid < 8) {
        float x = red[tid];
#pragma unroll
        for (int off = 4; off > 0; off >>= 1) x += __shfl_xor_sync(0xffu, x, off);
        if (tid == 0) red[0] = x;
    }
    __syncthreads();
    const float mean = red[0] / HCAT;
    __syncthreads();
    float vs = 0.f;
#pragma unroll
    for (int t = 0; t < 8; t++) { float d = v[t] - mean; vs += d * d; }
#pragma unroll
    for (int off = 16; off > 0; off >>= 1) vs += __shfl_xor_sync(0xffffffffu, vs, off);
    if ((tid & 31) == 0) red[tid >> 5] = vs;
    __syncthreads();
    if (tid < 8) {
        float x = red[tid];
#pragma unroll
        for (int off = 4; off > 0; off >>= 1) x += __shfl_xor_sync(0xffu, x, off);
        if (tid == 0) red[0] = x;
    }
    __syncthreads();
    const float rstd = rsqrtf(red[0] / HCAT + 1e-5f);
#pragma unroll
    for (int t = 0; t < 8; t++) {
        int c = tid + t * 256;
        float y = (v[t] - mean) * rstd * g[c] + b[c];
        y = y > 0.f ? y : (expf(y) - 1.f);      // elu after LN
        H1[(long)n * HCAT + c] = y;
    }
}

// ---------------- final: out = LN(sum_h HP1h + R1) ----------------
__global__ __launch_bounds__(256)
void final_kernel(const float* __restrict__ HP1h, const float* __restrict__ R,
                  const float* __restrict__ g, const float* __restrict__ b,
                  float* __restrict__ out)
{
    __shared__ float red[8];
    const int n = blockIdx.x;
    const int tid = threadIdx.x;
    float v[3];
    float sum = 0.f;
#pragma unroll
    for (int t = 0; t < 3; t++) {
        int c = tid + t * 256;
        long off = (long)n * DOUT + c;
        float x = R[off];
#pragma unroll
        for (int h = 0; h < H; h++)
            x += HP1h[(long)h * NN * DOUT + off];   // each slice pre-scaled by 0.25
        v[t] = x;
        sum += x;
    }
#pragma unroll
    for (int off = 16; off > 0; off >>= 1) sum += __shfl_xor_sync(0xffffffffu, sum, off);
    if ((tid & 31) == 0) red[tid >> 5] = sum;
    __syncthreads();
    if (tid < 8) {
        float x = red[tid];
#pragma unroll
        for (int off = 4; off > 0; off >>= 1) x += __shfl_xor_sync(0xffu, x, off);
        if (tid == 0) red[0] = x;
    }
    __syncthreads();
    const float mean = red[0] / DOUT;
    __syncthreads();
    float vs = 0.f;
#pragma unroll
    for (int t = 0; t < 3; t++) { float d = v[t] - mean; vs += d * d; }
#pragma unroll
    for (int off = 16; off > 0; off >>= 1) vs += __shfl_xor_sync(0xffffffffu, vs, off);
    if ((tid & 31) == 0) red[tid >> 5] = vs;
    __syncthreads();
    if (tid < 8) {
        float x = red[tid];
#pragma unroll
        for (int off = 4; off > 0; off >>= 1) x += __shfl_xor_sync(0xffu, x, off);
        if (tid == 0) red[0] = x;
    }
    __syncthreads();
    const float rstd = rsqrtf(red[0] / DOUT + 1e-5f);
#pragma unroll
    for (int t = 0; t < 3; t++) {
        int c = tid + t * 256;
        out[(long)n * DOUT + c] = (v[t] - mean) * rstd * g[c] + b[c];
    }
}

// ---------------- host ----------------
extern "C" void kernel_launch(void* const* d_in, const int* in_sizes, int n_in,
                              void* d_out, int out_size)
{
    const float* X    = (const float*)d_in[0];
    const int*   adj  = (const int*)  d_in[1];
    const float* ew   = (const float*)d_in[2];
    const float* W0   = (const float*)d_in[3];
    const float* a0   = (const float*)d_in[4];
    const float* W1   = (const float*)d_in[5];
    const float* a1   = (const float*)d_in[6];
    const float* rp0w = (const float*)d_in[7];
    const float* rp0b = (const float*)d_in[8];
    const float* rp1w = (const float*)d_in[9];
    const float* rp1b = (const float*)d_in[10];
    const float* ln0g = (const float*)d_in[11];
    const float* ln0b = (const float*)d_in[12];
    const float* ln1g = (const float*)d_in[13];
    const float* ln1b = (const float*)d_in[14];
    float* out = (float*)d_out;

    float *Wh0, *P, *ssrc, *sdst, *Hcat, *R, *H1, *Wh1, *HP1h;
    cudaGetSymbolAddress((void**)&Wh0,  g_Wh0);
    cudaGetSymbolAddress((void**)&P,    g_P);
    cudaGetSymbolAddress((void**)&ssrc, g_ssrc);
    cudaGetSymbolAddress((void**)&sdst, g_sdst);
    cudaGetSymbolAddress((void**)&Hcat, g_Hcat);
    cudaGetSymbolAddress((void**)&R,    g_R);
    cudaGetSymbolAddress((void**)&H1,   g_H1);
    cudaGetSymbolAddress((void**)&Wh1,  g_Wh1);
    cudaGetSymbolAddress((void**)&HP1h, g_HP1h);

    cudaFuncSetAttribute(tgemm_kernel, cudaFuncAttributeMaxDynamicSharedMemorySize,
                         GEMM_SMEM_BYTES);

    dim3 blk(256);

    // ===== Layer 0 =====
    // Wh0[h] = X @ W0[h] : M=4096 N=512 K=768
    {
        dim3 grid(HID / BN, NN / BM, H);
        tgemm_kernel<<<grid, blk, GEMM_SMEM_BYTES>>>(X, W0, Wh0, HID, DIN,
                                    0L, (long)DIN * HID, (long)NN * HID, HID,
                                    1.f, nullptr);
    }
    scores_kernel<<<(H * NN) / 8, blk>>>(Wh0, a0, ssrc, sdst, HID);
    {
        dim3 grid(NN, H);
        attn_kernel<<<grid, blk>>>(adj, ew, ssrc, sdst, P);
    }
    // Hcat[n, h*512+o] = P[h] @ Wh0[h] : M=4096 N=512 K=4096, ldc=2048
    {
        dim3 grid(HID / BN, NN / BM, H);
        tgemm_kernel<<<grid, blk, GEMM_SMEM_BYTES>>>(P, Wh0, Hcat, HID, NN,
                                    (long)NN * NN, (long)NN * HID, (long)HID, HCAT,
                                    1.f, nullptr);
    }
    // R = X @ rp0_w + rp0_b : M=4096 N=2048 K=768
    {
        dim3 grid(HCAT / BN, NN / BM, 1);
        tgemm_kernel<<<grid, blk, GEMM_SMEM_BYTES>>>(X, rp0w, R, HCAT, DIN,
                                    0L, 0L, 0L, HCAT,
                                    1.f, rp0b);
    }
    fuse0_kernel<<<NN, blk>>>(Hcat, R, ln0g, ln0b, H1);

    // ===== Layer 1 =====
    // Wh1[h] = H1 @ W1[h] : M=4096 N=768 K=2048
    {
        dim3 grid(DOUT / BN, NN / BM, H);
        tgemm_kernel<<<grid, blk, GEMM_SMEM_BYTES>>>(H1, W1, Wh1, DOUT, HCAT,
                                    0L, (long)HCAT * DOUT, (long)NN * DOUT, DOUT,
                                    1.f, nullptr);
    }
    scores_kernel<<<(H * NN) / 8, blk>>>(Wh1, a1, ssrc, sdst, DOUT);
    {
        dim3 grid(NN, H);
        attn_kernel<<<grid, blk>>>(adj, ew, ssrc, sdst, P);
    }
    // HP1h[h] = 0.25 * P[h] @ Wh1[h] : per-head, M=4096 N=768 K=4096, grid.z=4
    {
        dim3 grid(DOUT / BN, NN / BM, H);
        tgemm_kernel<<<grid, blk, GEMM_SMEM_BYTES>>>(P, Wh1, HP1h, DOUT, NN,
                                    (long)NN * NN, (long)NN * DOUT, (long)NN * DOUT, DOUT,
                                    0.25f, nullptr);
    }
    // R1 = H1 @ rp1_w + rp1_b : M=4096 N=768 K=2048
    {
        dim3 grid(DOUT / BN, NN / BM, 1);
        tgemm_kernel<<<grid, blk, GEMM_SMEM_BYTES>>>(H1, rp1w, R, DOUT, HCAT,
                                    0L, 0L, 0L, DOUT,
                                    1.f, rp1b);
    }
    final_kernel<<<NN, blk>>>(HP1h, R, ln1g, ln1b, out);
}

// round 5
// speedup vs baseline: 4.0651x; 1.1270x over previous
#include <cuda_runtime.h>
#include <math.h>
#include <stdint.h>

#define NN 4096      // nodes
#define DIN 768
#define HID 512
#define DOUT 768
#define H 4
#define HCAT (H*HID) // 2048
#define ALPHA 0.2f
#define NEG_BIG -9e15f

// ---------------- scratch (__device__ globals; no allocations) ----------------
__device__ float g_Wh0[(long)H * NN * HID];      // 32 MB (tf32-rounded)
__device__ float g_P[(long)H * NN * NN];         // 268 MB (tf32-rounded)
__device__ float g_ssrc[H * NN];
__device__ float g_sdst[H * NN];
__device__ float g_Hcat[(long)NN * HCAT];
__device__ float g_R[(long)NN * HCAT];
__device__ float g_H1[(long)NN * HCAT];          // tf32-rounded
__device__ float g_Wh1[(long)H * NN * DOUT];     // tf32-rounded
__device__ float g_HP1h[(long)H * NN * DOUT];
// tf32-rounded copies of inputs
__device__ float g_Xr[(long)NN * DIN];           // 12 MB
__device__ float g_W0r[(long)H * DIN * HID];     // 6 MB
__device__ float g_rp0wr[(long)DIN * HCAT];      // 6 MB
__device__ float g_W1r[(long)H * HCAT * DOUT];   // 25 MB
__device__ float g_rp1wr[(long)HCAT * DOUT];     // 6 MB

__device__ __forceinline__ uint32_t f2tf(float f) {
    uint32_t r;
    asm("cvt.rna.tf32.f32 %0, %1;" : "=r"(r) : "f"(f));
    return r;
}
__device__ __forceinline__ float roundtf(float f) { return __uint_as_float(f2tf(f)); }

// ---------------- tf32 pre-rounding pass ----------------
__global__ __launch_bounds__(256)
void round_kernel(const float* __restrict__ in, float* __restrict__ out, long n)
{
    long i = (long)(blockIdx.x * 256 + threadIdx.x) * 4;
    if (i >= n) return;
    float4 v = *(const float4*)(in + i);
    v.x = roundtf(v.x); v.y = roundtf(v.y); v.z = roundtf(v.z); v.w = roundtf(v.w);
    *(float4*)(out + i) = v;
}

// ================= tf32 tensor-core GEMM (3-stage cp.async, pre-rounded ops) =================
// C[z][m][n] (ldc) = scale * A[z*aB + m*K + k] * B[z*bB + k*N + n] (+bias[n])
#define BM 128
#define BN 128
#define BK 32
#define NSTAGE 3
#define LDA_S 36                    // padded A smem row (floats)
#define LDB_S 136                   // padded B smem row (floats)
#define A_STAGE (BM * LDA_S)        // 4608 floats
#define B_STAGE (BK * LDB_S)        // 4352 floats
#define STAGE_FLOATS (A_STAGE + B_STAGE)  // 8960
#define GEMM_SMEM_BYTES (NSTAGE * STAGE_FLOATS * 4)  // 107520 B

__device__ __forceinline__ void cp16(uint32_t s, const float* g) {
    asm volatile("cp.async.cg.shared.global [%0], [%1], 16;\n" :: "r"(s), "l"(g));
}

__device__ __forceinline__ void mma_tf32(float* d, const uint32_t* a, const uint32_t* b) {
    asm volatile(
        "mma.sync.aligned.m16n8k8.row.col.f32.tf32.tf32.f32 "
        "{%0,%1,%2,%3}, {%4,%5,%6,%7}, {%8,%9}, {%0,%1,%2,%3};"
        : "+f"(d[0]), "+f"(d[1]), "+f"(d[2]), "+f"(d[3])
        : "r"(a[0]), "r"(a[1]), "r"(a[2]), "r"(a[3]), "r"(b[0]), "r"(b[1]));
}

__global__ __launch_bounds__(256)
void tgemm_kernel(const float* __restrict__ A, const float* __restrict__ B,
                  float* __restrict__ C,
                  int N, int K,
                  long aBatch, long bBatch, long cBatch, int ldc,
                  float scale, const float* __restrict__ bias, int roundOut)
{
    extern __shared__ float smem[];
    const int tid = threadIdx.x;
    const int w = tid >> 5, lane = tid & 31;
    const int wm = w >> 1, wn = w & 1;       // 4x2 warp grid
    const int g = lane >> 2, tg = lane & 3;  // groupID, thread-in-group

    const int bz = blockIdx.z;
    const float* Ab = A + (long)bz * aBatch;
    const float* Bb = B + (long)bz * bBatch;
    float* Cb = C + (long)bz * cBatch;
    const int bm = blockIdx.y * BM;
    const int bn = blockIdx.x * BN;

    float acc[2][8][4];
#pragma unroll
    for (int mi = 0; mi < 2; mi++)
#pragma unroll
        for (int ni = 0; ni < 8; ni++)
#pragma unroll
            for (int q = 0; q < 4; q++) acc[mi][ni][q] = 0.f;

    const int nk = K / BK;
    uint32_t smem_u32 = (uint32_t)__cvta_generic_to_shared(smem);

    int ar[4], ac[4], br4[4], bc4[4];
#pragma unroll
    for (int i = 0; i < 4; i++) {
        int c = tid + i * 256;
        ar[i] = c >> 3;  ac[i] = (c & 7) * 4;
        br4[i] = c >> 5; bc4[i] = (c & 31) * 4;
    }

#pragma unroll
    for (int s = 0; s < 2; s++) {
        uint32_t abase = smem_u32 + s * STAGE_FLOATS * 4;
        uint32_t bbase = abase + A_STAGE * 4;
        const long koff = (long)s * BK;
#pragma unroll
        for (int i = 0; i < 4; i++) {
            cp16(abase + (ar[i] * LDA_S + ac[i]) * 4,
                 Ab + (long)(bm + ar[i]) * K + koff + ac[i]);
            cp16(bbase + (br4[i] * LDB_S + bc4[i]) * 4,
                 Bb + (koff + br4[i]) * N + bn + bc4[i]);
        }
        asm volatile("cp.async.commit_group;\n");
    }

    for (int kt = 0; kt < nk; ++kt) {
        if (kt + 1 < nk) asm volatile("cp.async.wait_group 1;\n");
        else             asm volatile("cp.async.wait_group 0;\n");
        __syncthreads();

        const uint32_t* As = (const uint32_t*)(smem + (kt % NSTAGE) * STAGE_FLOATS);
        const uint32_t* Bs = As + A_STAGE;

#pragma unroll
        for (int k0 = 0; k0 < 4; k0++) {
            uint32_t afr[2][4];
#pragma unroll
            for (int mi = 0; mi < 2; mi++) {
                int r = wm * 32 + mi * 16 + g;
                int cidx = k0 * 8 + tg;
                afr[mi][0] = As[r * LDA_S + cidx];
                afr[mi][1] = As[(r + 8) * LDA_S + cidx];
                afr[mi][2] = As[r * LDA_S + cidx + 4];
                afr[mi][3] = As[(r + 8) * LDA_S + cidx + 4];
            }
            uint32_t bfr[8][2];
#pragma unroll
            for (int ni = 0; ni < 8; ni++) {
                int col = wn * 64 + ni * 8 + g;
                int row = k0 * 8 + tg;
                bfr[ni][0] = Bs[row * LDB_S + col];
                bfr[ni][1] = Bs[(row + 4) * LDB_S + col];
            }
#pragma unroll
            for (int mi = 0; mi < 2; mi++)
#pragma unroll
                for (int ni = 0; ni < 8; ni++)
                    mma_tf32(acc[mi][ni], afr[mi], bfr[ni]);
        }

        if (kt + 2 < nk) {
            int s = (kt + 2) % NSTAGE;
            uint32_t abase = smem_u32 + s * STAGE_FLOATS * 4;
            uint32_t bbase = abase + A_STAGE * 4;
            const long koff = (long)(kt + 2) * BK;
#pragma unroll
            for (int i = 0; i < 4; i++) {
                cp16(abase + (ar[i] * LDA_S + ac[i]) * 4,
                     Ab + (long)(bm + ar[i]) * K + koff + ac[i]);
                cp16(bbase + (br4[i] * LDB_S + bc4[i]) * 4,
                     Bb + (koff + br4[i]) * N + bn + bc4[i]);
            }
            asm volatile("cp.async.commit_group;\n");
        } else {
            asm volatile("cp.async.commit_group;\n");
        }
    }

    // epilogue
#pragma unroll
    for (int mi = 0; mi < 2; mi++) {
        int r0 = bm + wm * 32 + mi * 16 + g;
#pragma unroll
        for (int ni = 0; ni < 8; ni++) {
            int c0 = bn + wn * 64 + ni * 8 + 2 * tg;
            float b0 = bias ? bias[c0] : 0.f;
            float b1 = bias ? bias[c0 + 1] : 0.f;
            float v0 = acc[mi][ni][0] * scale + b0;
            float v1 = acc[mi][ni][1] * scale + b1;
            float v2 = acc[mi][ni][2] * scale + b0;
            float v3 = acc[mi][ni][3] * scale + b1;
            if (roundOut) {
                v0 = roundtf(v0); v1 = roundtf(v1);
                v2 = roundtf(v2); v3 = roundtf(v3);
            }
            *(float2*)&Cb[(long)r0 * ldc + c0] = make_float2(v0, v1);
            *(float2*)&Cb[(long)(r0 + 8) * ldc + c0] = make_float2(v2, v3);
        }
    }
}

// ---------------- scores: s = Wh . a  (src and dst halves) ----------------
__global__ void scores_kernel(const float* __restrict__ Wh, const float* __restrict__ a,
                              float* __restrict__ ssrc, float* __restrict__ sdst, int O)
{
    int warp = (blockIdx.x * blockDim.x + threadIdx.x) >> 5;
    int lane = threadIdx.x & 31;
    if (warp >= H * NN) return;
    int h = warp / NN;
    int n = warp % NN;
    const float* row = Wh + ((long)h * NN + n) * O;
    const float* a1 = a + (long)h * 2 * O;
    const float* a2 = a1 + O;
    float s1 = 0.f, s2 = 0.f;
    for (int o = lane; o < O; o += 32) {
        float v = row[o];
        s1 += v * a1[o];
        s2 += v * a2[o];
    }
#pragma unroll
    for (int off = 16; off > 0; off >>= 1) {
        s1 += __shfl_xor_sync(0xffffffffu, s1, off);
        s2 += __shfl_xor_sync(0xffffffffu, s2, off);
    }
    if (lane == 0) { ssrc[h * NN + n] = s1; sdst[h * NN + n] = s2; }
}

// ---------------- attention row softmax -> P (tf32-rounded) ----------------
__global__ __launch_bounds__(256)
void attn_kernel(const int* __restrict__ adj, const float* __restrict__ ew,
                 const float* __restrict__ ssrc, const float* __restrict__ sdst,
                 float* __restrict__ P)
{
    __shared__ float sl[NN];
    __shared__ float red[8];
    const int i = blockIdx.x;
    const int h = blockIdx.y;
    const int tid = threadIdx.x;
    const float si = ssrc[h * NN + i];
    const float* sd = sdst + h * NN;
    const long rowbase = (long)i * NN;

    float lmax = -INFINITY;
    for (int j = tid; j < NN; j += 256) {
        int am = adj[rowbase + j];
        float w = ew[rowbase + j];
        bool m = (am > 0) || (j == i);
        float x = si + sd[j];
        float lr = x > 0.f ? x : ALPHA * x;
        float l = (m ? lr : NEG_BIG) * w;
        sl[j] = l;
        lmax = fmaxf(lmax, l);
    }
#pragma unroll
    for (int off = 16; off > 0; off >>= 1) lmax = fmaxf(lmax, __shfl_xor_sync(0xffffffffu, lmax, off));
    if ((tid & 31) == 0) red[tid >> 5] = lmax;
    __syncthreads();
    if (tid < 8) {
        float v = red[tid];
#pragma unroll
        for (int off = 4; off > 0; off >>= 1) v = fmaxf(v, __shfl_xor_sync(0xffu, v, off));
        if (tid == 0) red[0] = v;
    }
    __syncthreads();
    const float rowmax = red[0];
    __syncthreads();

    float lsum = 0.f;
    for (int j = tid; j < NN; j += 256) {
        float e = __expf(sl[j] - rowmax);
        sl[j] = e;
        lsum += e;
    }
#pragma unroll
    for (int off = 16; off > 0; off >>= 1) lsum += __shfl_xor_sync(0xffffffffu, lsum, off);
    if ((tid & 31) == 0) red[tid >> 5] = lsum;
    __syncthreads();
    if (tid < 8) {
        float v = red[tid];
#pragma unroll
        for (int off = 4; off > 0; off >>= 1) v += __shfl_xor_sync(0xffu, v, off);
        if (tid == 0) red[0] = v;
    }
    __syncthreads();
    const float inv = 1.f / red[0];

    float* prow = P + ((long)h * NN + i) * NN;
    for (int j = tid; j < NN; j += 256) prow[j] = roundtf(sl[j] * inv);
}

// ---------------- layer-0 epilogue: H1 = elu(LN(elu(Hcat)+R)), tf32-rounded ----------------
__global__ __launch_bounds__(256)
void fuse0_kernel(const float* __restrict__ Hcat, const float* __restrict__ R,
                  const float* __restrict__ g, const float* __restrict__ b,
                  float* __restrict__ H1)
{
    __shared__ float red[8];
    const int n = blockIdx.x;
    const int tid = threadIdx.x;
    float v[8];
    float sum = 0.f;
#pragma unroll
    for (int t = 0; t < 8; t++) {
        int c = tid + t * 256;
        float x = Hcat[(long)n * HCAT + c];
        x = x > 0.f ? x : (expf(x) - 1.f);
        x += R[(long)n * HCAT + c];
        v[t] = x;
        sum += x;
    }
#pragma unroll
    for (int off = 16; off > 0; off >>= 1) sum += __shfl_xor_sync(0xffffffffu, sum, off);
    if ((tid & 31) == 0) red[tid >> 5] = sum;
    __syncthreads();
    if (tid < 8) {
        float x = red[tid];
#pragma unroll
        for (int off = 4; off > 0; off >>= 1) x += __shfl_xor_sync(0xffu, x, off);
        if (tid == 0) red[0] = x;
    }
    __syncthreads();
    const float mean = red[0] / HCAT;
    __syncthreads();
    float vs = 0.f;
#pragma unroll
    for (int t = 0; t < 8; t++) { float d = v[t] - mean; vs += d * d; }
#pragma unroll
    for (int off = 16; off > 0; off >>= 1) vs += __shfl_xor_sync(0xffffffffu, vs, off);
    if ((tid & 31) == 0) red[tid >> 5] = vs;
    __syncthreads();
    if (tid < 8) {
        float x = red[tid];
#pragma unroll
        for (int off = 4; off > 0; off >>= 1) x += __shfl_xor_sync(0xffu, x, off);
        if (tid == 0) red[0] = x;
    }
    __syncthreads();
    const float rstd = rsqrtf(red[0] / HCAT + 1e-5f);
#pragma unroll
    for (int t = 0; t < 8; t++) {
        int c = tid + t * 256;
        float y = (v[t] - mean) * rstd * g[c] + b[c];
        y = y > 0.f ? y : (expf(y) - 1.f);
        H1[(long)n * HCAT + c] = roundtf(y);
    }
}

// ---------------- final: out = LN(sum_h HP1h + R1) ----------------
__global__ __launch_bounds__(256)
void final_kernel(const float* __restrict__ HP1h, const float* __restrict__ R,
                  const float* __restrict__ g, const float* __restrict__ b,
                  float* __restrict__ out)
{
    __shared__ float red[8];
    const int n = blockIdx.x;
    const int tid = threadIdx.x;
    float v[3];
    float sum = 0.f;
#pragma unroll
    for (int t = 0; t < 3; t++) {
        int c = tid + t * 256;
        long off = (long)n * DOUT + c;
        float x = R[off];
#pragma unroll
        for (int h = 0; h < H; h++)
            x += HP1h[(long)h * NN * DOUT + off];
        v[t] = x;
        sum += x;
    }
#pragma unroll
    for (int off = 16; off > 0; off >>= 1) sum += __shfl_xor_sync(0xffffffffu, sum, off);
    if ((tid & 31) == 0) red[tid >> 5] = sum;
    __syncthreads();
    if (tid < 8) {
        float x = red[tid];
#pragma unroll
        for (int off = 4; off > 0; off >>= 1) x += __shfl_xor_sync(0xffu, x, off);
        if (tid == 0) red[0] = x;
    }
    __syncthreads();
    const float mean = red[0] / DOUT;
    __syncthreads();
    float vs = 0.f;
#pragma unroll
    for (int t = 0; t < 3; t++) { float d = v[t] - mean; vs += d * d; }
#pragma unroll
    for (int off = 16; off > 0; off >>= 1) vs += __shfl_xor_sync(0xffffffffu, vs, off);
    if ((tid & 31) == 0) red[tid >> 5] = vs;
    __syncthreads();
    if (tid < 8) {
        float x = red[tid];
#pragma unroll
        for (int off = 4; off > 0; off >>= 1) x += __shfl_xor_sync(0xffu, x, off);
        if (tid == 0) red[0] = x;
    }
    __syncthreads();
    const float rstd = rsqrtf(red[0] / DOUT + 1e-5f);
#pragma unroll
    for (int t = 0; t < 3; t++) {
        int c = tid + t * 256;
        out[(long)n * DOUT + c] = (v[t] - mean) * rstd * g[c] + b[c];
    }
}

// ---------------- host ----------------
extern "C" void kernel_launch(void* const* d_in, const int* in_sizes, int n_in,
                              void* d_out, int out_size)
{
    const float* X    = (const float*)d_in[0];
    const int*   adj  = (const int*)  d_in[1];
    const float* ew   = (const float*)d_in[2];
    const float* W0   = (const float*)d_in[3];
    const float* a0   = (const float*)d_in[4];
    const float* W1   = (const float*)d_in[5];
    const float* a1   = (const float*)d_in[6];
    const float* rp0w = (const float*)d_in[7];
    const float* rp0b = (const float*)d_in[8];
    const float* rp1w = (const float*)d_in[9];
    const float* rp1b = (const float*)d_in[10];
    const float* ln0g = (const float*)d_in[11];
    const float* ln0b = (const float*)d_in[12];
    const float* ln1g = (const float*)d_in[13];
    const float* ln1b = (const float*)d_in[14];
    float* out = (float*)d_out;

    float *Wh0, *P, *ssrc, *sdst, *Hcat, *R, *H1, *Wh1, *HP1h;
    float *Xr, *W0r, *rp0wr, *W1r, *rp1wr;
    cudaGetSymbolAddress((void**)&Wh0,  g_Wh0);
    cudaGetSymbolAddress((void**)&P,    g_P);
    cudaGetSymbolAddress((void**)&ssrc, g_ssrc);
    cudaGetSymbolAddress((void**)&sdst, g_sdst);
    cudaGetSymbolAddress((void**)&Hcat, g_Hcat);
    cudaGetSymbolAddress((void**)&R,    g_R);
    cudaGetSymbolAddress((void**)&H1,   g_H1);
    cudaGetSymbolAddress((void**)&Wh1,  g_Wh1);
    cudaGetSymbolAddress((void**)&HP1h, g_HP1h);
    cudaGetSymbolAddress((void**)&Xr,    g_Xr);
    cudaGetSymbolAddress((void**)&W0r,   g_W0r);
    cudaGetSymbolAddress((void**)&rp0wr, g_rp0wr);
    cudaGetSymbolAddress((void**)&W1r,   g_W1r);
    cudaGetSymbolAddress((void**)&rp1wr, g_rp1wr);

    cudaFuncSetAttribute(tgemm_kernel, cudaFuncAttributeMaxDynamicSharedMemorySize,
                         GEMM_SMEM_BYTES);

    dim3 blk(256);

    // pre-round inputs to tf32
    {
        long n;
        n = (long)NN * DIN;        round_kernel<<<(n/4 + 255)/256, blk>>>(X, Xr, n);
        n = (long)H * DIN * HID;   round_kernel<<<(n/4 + 255)/256, blk>>>(W0, W0r, n);
        n = (long)DIN * HCAT;      round_kernel<<<(n/4 + 255)/256, blk>>>(rp0w, rp0wr, n);
        n = (long)H * HCAT * DOUT; round_kernel<<<(n/4 + 255)/256, blk>>>(W1, W1r, n);
        n = (long)HCAT * DOUT;     round_kernel<<<(n/4 + 255)/256, blk>>>(rp1w, rp1wr, n);
    }

    // ===== Layer 0 =====
    // Wh0[h] = Xr @ W0r[h] : M=4096 N=512 K=768 (round output: consumed as GEMM/dot operand)
    {
        dim3 grid(HID / BN, NN / BM, H);
        tgemm_kernel<<<grid, blk, GEMM_SMEM_BYTES>>>(Xr, W0r, Wh0, HID, DIN,
                                    0L, (long)DIN * HID, (long)NN * HID, HID,
                                    1.f, nullptr, 1);
    }
    scores_kernel<<<(H * NN) / 8, blk>>>(Wh0, a0, ssrc, sdst, HID);
    {
        dim3 grid(NN, H);
        attn_kernel<<<grid, blk>>>(adj, ew, ssrc, sdst, P);
    }
    // Hcat = P[h] @ Wh0[h] : M=4096 N=512 K=4096, ldc=2048 (no round: feeds fuse0)
    {
        dim3 grid(HID / BN, NN / BM, H);
        tgemm_kernel<<<grid, blk, GEMM_SMEM_BYTES>>>(P, Wh0, Hcat, HID, NN,
                                    (long)NN * NN, (long)NN * HID, (long)HID, HCAT,
                                    1.f, nullptr, 0);
    }
    // R = Xr @ rp0wr + rp0b : M=4096 N=2048 K=768 (no round)
    {
        dim3 grid(HCAT / BN, NN / BM, 1);
        tgemm_kernel<<<grid, blk, GEMM_SMEM_BYTES>>>(Xr, rp0wr, R, HCAT, DIN,
                                    0L, 0L, 0L, HCAT,
                                    1.f, rp0b, 0);
    }
    fuse0_kernel<<<NN, blk>>>(Hcat, R, ln0g, ln0b, H1);   // H1 rounded at write

    // ===== Layer 1 =====
    // Wh1[h] = H1 @ W1r[h] : M=4096 N=768 K=2048 (round output)
    {
        dim3 grid(DOUT / BN, NN / BM, H);
        tgemm_kernel<<<grid, blk, GEMM_SMEM_BYTES>>>(H1, W1r, Wh1, DOUT, HCAT,
                                    0L, (long)HCAT * DOUT, (long)NN * DOUT, DOUT,
                                    1.f, nullptr, 1);
    }
    scores_kernel<<<(H * NN) / 8, blk>>>(Wh1, a1, ssrc, sdst, DOUT);
    {
        dim3 grid(NN, H);
        attn_kernel<<<grid, blk>>>(adj, ew, ssrc, sdst, P);
    }
    // HP1h[h] = 0.25 * P[h] @ Wh1[h] : per-head (no round: feeds final LN)
    {
        dim3 grid(DOUT / BN, NN / BM, H);
        tgemm_kernel<<<grid, blk, GEMM_SMEM_BYTES>>>(P, Wh1, HP1h, DOUT, NN,
                                    (long)NN * NN, (long)NN * DOUT, (long)NN * DOUT, DOUT,
                                    0.25f, nullptr, 0);
    }
    // R1 = H1 @ rp1wr + rp1b : M=4096 N=768 K=2048 (no round)
    {
        dim3 grid(DOUT / BN, NN / BM, 1);
        tgemm_kernel<<<grid, blk, GEMM_SMEM_BYTES>>>(H1, rp1wr, R, DOUT, HCAT,
                                    0L, 0L, 0L, DOUT,
                                    1.f, rp1b, 0);
    }
    final_kernel<<<NN, blk>>>(HP1h, R, ln1g, ln1b, out);
}

// round 7
// speedup vs baseline: 5.5907x; 1.3753x over previous
#include <cuda_runtime.h>
#include <cuda_fp16.h>
#include <math.h>
#include <stdint.h>

#define NN 4096      // nodes
#define DIN 768
#define HID 512
#define DOUT 768
#define H 4
#define HCAT (H*HID) // 2048
#define ALPHA 0.2f
#define NEG_BIG -9e15f

// ---------------- scratch (__device__ globals; no allocations) ----------------
__device__ __half g_Xh[(long)NN * DIN];            // fp16 X
__device__ __half g_W0T[(long)H * HID * DIN];      // W0 transposed [h][o][f]
__device__ __half g_rp0T[(long)HCAT * DIN];        // rp0_w transposed
__device__ __half g_W1T[(long)H * DOUT * HCAT];    // W1 transposed
__device__ __half g_rp1T[(long)DOUT * HCAT];       // rp1_w transposed
__device__ __half g_Wh0T[(long)H * HID * NN];      // Wh0 transposed [h][o][n]
__device__ __half g_Wh1T[(long)H * DOUT * NN];     // Wh1 transposed
__device__ __half g_P[(long)H * NN * NN];          // softmax weights fp16 (134 MB)
__device__ __half g_H1[(long)NN * HCAT];           // layer-0 output fp16
__device__ float  g_ssrc[H * NN];
__device__ float  g_sdst[H * NN];
__device__ float  g_Hcat[(long)NN * HCAT];
__device__ float  g_R[(long)NN * HCAT];
__device__ float  g_HP1h[(long)H * NN * DOUT];

// ================= fp16 mma.sync GEMM (3-stage cp.async) =================
// C[z][m][n] = scale * sum_k A[z*aB + (bm+m)*K + k] * B[z*bB + (bn+n)*K + k] (+bias[n])
// A: [M][K] fp16 row-major. B: [N][K] fp16 K-major. transH: store half C^T.
#define BM 128
#define BN 128
#define BKH 32                       // halves per stage k-depth
#define NST 3
#define LDH 40                       // padded halves per smem row
#define LDW (LDH/2)                  // u32 stride = 20
#define A_ST (BM * LDH)              // 5120 halves
#define B_ST (BN * LDH)              // 5120 halves
#define STG_H (A_ST + B_ST)          // 10240 halves
#define GEMM_SMEM (NST * STG_H * 2)  // 61440 bytes

__device__ __forceinline__ void cp16(uint32_t s, const void* g) {
    asm volatile("cp.async.cg.shared.global [%0], [%1], 16;\n" :: "r"(s), "l"(g));
}

__device__ __forceinline__ void mma_f16(float* d, const uint32_t* a, const uint32_t* b) {
    asm volatile(
        "mma.sync.aligned.m16n8k16.row.col.f32.f16.f16.f32 "
        "{%0,%1,%2,%3}, {%4,%5,%6,%7}, {%8,%9}, {%0,%1,%2,%3};"
        : "+f"(d[0]), "+f"(d[1]), "+f"(d[2]), "+f"(d[3])
        : "r"(a[0]), "r"(a[1]), "r"(a[2]), "r"(a[3]), "r"(b[0]), "r"(b[1]));
}

__global__ __launch_bounds__(256)
void hgemm_mma(const __half* __restrict__ A, const __half* __restrict__ B, void* Cv,
               int K, long aB, long bB, long cB, int ldc,
               float scale, const float* __restrict__ bias, int transH)
{
    extern __shared__ __half smh[];
    const int tid = threadIdx.x;
    const int w = tid >> 5, lane = tid & 31;
    const int wm = w >> 1, wn = w & 1;       // 4x2 warp grid (warp tile 32x64)
    const int g = lane >> 2, tg = lane & 3;

    const int bz = blockIdx.z;
    const int bm = blockIdx.y * BM;
    const int bn = blockIdx.x * BN;
    const __half* Abase = A + (long)bz * aB + (long)bm * K;
    const __half* Bbase = B + (long)bz * bB + (long)bn * K;

    float acc[2][8][4];
#pragma unroll
    for (int mi = 0; mi < 2; mi++)
#pragma unroll
        for (int ni = 0; ni < 8; ni++)
#pragma unroll
            for (int q = 0; q < 4; q++) acc[mi][ni][q] = 0.f;

    uint32_t smem_u32;
    asm("{ .reg .u64 t; cvta.to.shared.u64 t, %1; cvt.u32.u64 %0, t; }"
        : "=r"(smem_u32) : "l"(smh));

    // per-thread cp.async chunks: 2 A + 2 B per stage (each chunk 16B = 8 halves)
    int crow[2], ccol[2];
#pragma unroll
    for (int i = 0; i < 2; i++) {
        int c = tid + i * 256;
        crow[i] = c >> 2;             // 0..127
        ccol[i] = (c & 3) * 8;        // half offset 0/8/16/24
    }
    const int nk = K / BKH;

    auto load_stage = [&](int slot, int kt) {
        uint32_t sa = smem_u32 + slot * STG_H * 2;
        uint32_t sb = sa + A_ST * 2;
        long ko = (long)kt * BKH;
#pragma unroll
        for (int i = 0; i < 2; i++) {
            cp16(sa + (crow[i] * LDH + ccol[i]) * 2,
                 Abase + (long)crow[i] * K + ko + ccol[i]);
            cp16(sb + (crow[i] * LDH + ccol[i]) * 2,
                 Bbase + (long)crow[i] * K + ko + ccol[i]);
        }
    };

    load_stage(0, 0); asm volatile("cp.async.commit_group;\n");
    load_stage(1, 1); asm volatile("cp.async.commit_group;\n");

    for (int kt = 0; kt < nk; ++kt) {
        if (kt + 1 < nk) asm volatile("cp.async.wait_group 1;\n");
        else             asm volatile("cp.async.wait_group 0;\n");
        __syncthreads();

        const uint32_t* As = (const uint32_t*)(smh + (kt % NST) * STG_H);
        const uint32_t* Bs = As + A_ST / 2;

#pragma unroll
        for (int k0 = 0; k0 < 2; k0++) {       // two k16 steps per stage
            uint32_t afr[2][4];
#pragma unroll
            for (int mi = 0; mi < 2; mi++) {
                int r = wm * 32 + mi * 16 + g;
                int base = r * LDW + tg + k0 * 8;
                afr[mi][0] = As[base];
                afr[mi][1] = As[base + 8 * LDW];
                afr[mi][2] = As[base + 4];
                afr[mi][3] = As[base + 8 * LDW + 4];
            }
            uint32_t bfr[8][2];
#pragma unroll
            for (int ni = 0; ni < 8; ni++) {
                int n = wn * 64 + ni * 8 + g;
                int base = n * LDW + tg + k0 * 8;
                bfr[ni][0] = Bs[base];
                bfr[ni][1] = Bs[base + 4];
            }
#pragma unroll
            for (int mi = 0; mi < 2; mi++)
#pragma unroll
                for (int ni = 0; ni < 8; ni++)
                    mma_f16(acc[mi][ni], afr[mi], bfr[ni]);
        }

        if (kt + 2 < nk) load_stage((kt + 2) % NST, kt + 2);
        asm volatile("cp.async.commit_group;\n");
    }

    // epilogue: acc[mi][ni] = {(r0,c0),(r0,c0+1),(r0+8,c0),(r0+8,c0+1)}
#pragma unroll
    for (int mi = 0; mi < 2; mi++) {
        int r0 = bm + wm * 32 + mi * 16 + g;
#pragma unroll
        for (int ni = 0; ni < 8; ni++) {
            int c0 = bn + wn * 64 + ni * 8 + 2 * tg;
            if (!transH) {
                float* Cf = (float*)Cv + (long)bz * cB;
                float b0 = bias ? bias[c0] : 0.f;
                float b1 = bias ? bias[c0 + 1] : 0.f;
                *(float2*)&Cf[(long)r0 * ldc + c0] =
                    make_float2(acc[mi][ni][0] * scale + b0, acc[mi][ni][1] * scale + b1);
                *(float2*)&Cf[(long)(r0 + 8) * ldc + c0] =
                    make_float2(acc[mi][ni][2] * scale + b0, acc[mi][ni][3] * scale + b1);
            } else {
                __half* Ch = (__half*)Cv + (long)bz * cB;
                Ch[(long)c0 * NN + r0]           = __float2half_rn(acc[mi][ni][0] * scale);
                Ch[(long)(c0 + 1) * NN + r0]     = __float2half_rn(acc[mi][ni][1] * scale);
                Ch[(long)c0 * NN + r0 + 8]       = __float2half_rn(acc[mi][ni][2] * scale);
                Ch[(long)(c0 + 1) * NN + r0 + 8] = __float2half_rn(acc[mi][ni][3] * scale);
            }
        }
    }
}

// ---------------- transpose f32 -> fp16 : out[b][c][r] = in[b][r][c] ----------------
__global__ void transpose_h(const float* __restrict__ in, __half* __restrict__ out,
                            int R, int C)
{
    __shared__ float t[32][33];
    long ib = (long)blockIdx.z * R * C;
    int c0 = blockIdx.x * 32, r0 = blockIdx.y * 32;
    int tx = threadIdx.x, ty = threadIdx.y;
#pragma unroll
    for (int i = 0; i < 4; i++)
        t[ty + i * 8][tx] = in[ib + (long)(r0 + ty + i * 8) * C + c0 + tx];
    __syncthreads();
#pragma unroll
    for (int i = 0; i < 4; i++)
        out[ib + (long)(c0 + ty + i * 8) * R + r0 + tx] = __float2half_rn(t[tx][ty + i * 8]);
}

// ---------------- f32 -> fp16 convert ----------------
__global__ void conv_half(const float* __restrict__ in, __half* __restrict__ out, long n)
{
    long i = ((long)blockIdx.x * 256 + threadIdx.x) * 4;
    if (i >= n) return;
    float4 v = *(const float4*)(in + i);
    *(__half2*)(out + i)     = __floats2half2_rn(v.x, v.y);
    *(__half2*)(out + i + 2) = __floats2half2_rn(v.z, v.w);
}

// ---------------- scores from WhT: s[n] = sum_o WhT[h][o][n] * a[o] ----------------
__global__ __launch_bounds__(256)
void scores_kernel(const __half* __restrict__ WhT, const float* __restrict__ a,
                   float* __restrict__ ssrc, float* __restrict__ sdst, int O)
{
    int n = blockIdx.x * 256 + threadIdx.x;
    int h = blockIdx.y;
    const __half* base = WhT + (long)h * O * NN + n;
    const float* a1 = a + (long)h * 2 * O;
    const float* a2 = a1 + O;
    float s1 = 0.f, s2 = 0.f;
#pragma unroll 4
    for (int o = 0; o < O; o++) {
        float v = __half2float(base[(long)o * NN]);
        s1 += v * a1[o];
        s2 += v * a2[o];
    }
    ssrc[h * NN + n] = s1;
    sdst[h * NN + n] = s2;
}

// ---------------- attention row softmax -> P (fp16) ----------------
__global__ __launch_bounds__(256)
void attn_kernel(const int* __restrict__ adj, const float* __restrict__ ew,
                 const float* __restrict__ ssrc, const float* __restrict__ sdst,
                 __half* __restrict__ P)
{
    __shared__ float sl[NN];
    __shared__ float red[8];
    const int i = blockIdx.x;
    const int h = blockIdx.y;
    const int tid = threadIdx.x;
    const float si = ssrc[h * NN + i];
    const float* sd = sdst + h * NN;
    const long rowbase = (long)i * NN;

    float lmax = -INFINITY;
    for (int j = tid; j < NN; j += 256) {
        int am = adj[rowbase + j];
        float wv = ew[rowbase + j];
        bool m = (am > 0) || (j == i);
        float x = si + sd[j];
        float lr = x > 0.f ? x : ALPHA * x;
        float l = (m ? lr : NEG_BIG) * wv;
        sl[j] = l;
        lmax = fmaxf(lmax, l);
    }
#pragma unroll
    for (int off = 16; off > 0; off >>= 1) lmax = fmaxf(lmax, __shfl_xor_sync(0xffffffffu, lmax, off));
    if ((tid & 31) == 0) red[tid >> 5] = lmax;
    __syncthreads();
    if (tid < 8) {
        float v = red[tid];
#pragma unroll
        for (int off = 4; off > 0; off >>= 1) v = fmaxf(v, __shfl_xor_sync(0xffu, v, off));
        if (tid == 0) red[0] = v;
    }
    __syncthreads();
    const float rowmax = red[0];
    __syncthreads();

    float lsum = 0.f;
    for (int j = tid; j < NN; j += 256) {
        float e = __expf(sl[j] - rowmax);
        sl[j] = e;
        lsum += e;
    }
#pragma unroll
    for (int off = 16; off > 0; off >>= 1) lsum += __shfl_xor_sync(0xffffffffu, lsum, off);
    if ((tid & 31) == 0) red[tid >> 5] = lsum;
    __syncthreads();
    if (tid < 8) {
        float v = red[tid];
#pragma unroll
        for (int off = 4; off > 0; off >>= 1) v += __shfl_xor_sync(0xffu, v, off);
        if (tid == 0) red[0] = v;
    }
    __syncthreads();
    const float inv = 1.f / red[0];

    __half* prow = P + ((long)h * NN + i) * NN;
    for (int j = tid; j < NN; j += 256) prow[j] = __float2half_rn(sl[j] * inv);
}

// ---------------- layer-0 epilogue: H1 = elu(LN(elu(Hcat)+R)) -> fp16 ----------------
__global__ __launch_bounds__(256)
void fuse0_kernel(const float* __restrict__ Hcat, const float* __restrict__ R,
                  const float* __restrict__ g, const float* __restrict__ b,
                  __half* __restrict__ H1)
{
    __shared__ float red[8];
    const int n = blockIdx.x;
    const int tid = threadIdx.x;
    float v[8];
    float sum = 0.f;
#pragma unroll
    for (int t = 0; t < 8; t++) {
        int c = tid + t * 256;
        float x = Hcat[(long)n * HCAT + c];
        x = x > 0.f ? x : (expf(x) - 1.f);
        x += R[(long)n * HCAT + c];
        v[t] = x;
        sum += x;
    }
#pragma unroll
    for (int off = 16; off > 0; off >>= 1) sum += __shfl_xor_sync(0xffffffffu, sum, off);
    if ((tid & 31) == 0) red[tid >> 5] = sum;
    __syncthreads();
    if (tid < 8) {
        float x = red[tid];
#pragma unroll
        for (int off = 4; off > 0; off >>= 1) x += __shfl_xor_sync(0xffu, x, off);
        if (tid == 0) red[0] = x;
    }
    __syncthreads();
    const float mean = red[0] / HCAT;
    __syncthreads();
    float vs = 0.f;
#pragma unroll
    for (int t = 0; t < 8; t++) { float d = v[t] - mean; vs += d * d; }
#pragma unroll
    for (int off = 16; off > 0; off >>= 1) vs += __shfl_xor_sync(0xffffffffu, vs, off);
    if ((tid & 31) == 0) red[tid >> 5] = vs;
    __syncthreads();
    if (tid < 8) {
        float x = red[tid];
#pragma unroll
        for (int off = 4; off > 0; off >>= 1) x += __shfl_xor_sync(0xffu, x, off);
        if (tid == 0) red[0] = x;
    }
    __syncthreads();
    const float rstd = rsqrtf(red[0] / HCAT + 1e-5f);
#pragma unroll
    for (int t = 0; t < 8; t++) {
        int c = tid + t * 256;
        float y = (v[t] - mean) * rstd * g[c] + b[c];
        y = y > 0.f ? y : (expf(y) - 1.f);
        H1[(long)n * HCAT + c] = __float2half_rn(y);
    }
}

// ---------------- final: out = LN(sum_h HP1h + R1) ----------------
__global__ __launch_bounds__(256)
void final_kernel(const float* __restrict__ HP1h, const float* __restrict__ R,
                  const float* __restrict__ g, const float* __restrict__ b,
                  float* __restrict__ out)
{
    __shared__ float red[8];
    const int n = blockIdx.x;
    const int tid = threadIdx.x;
    float v[3];
    float sum = 0.f;
#pragma unroll
    for (int t = 0; t < 3; t++) {
        int c = tid + t * 256;
        long off = (long)n * DOUT + c;
        float x = R[off];
#pragma unroll
        for (int h = 0; h < H; h++)
            x += HP1h[(long)h * NN * DOUT + off];
        v[t] = x;
        sum += x;
    }
#pragma unroll
    for (int off = 16; off > 0; off >>= 1) sum += __shfl_xor_sync(0xffffffffu, sum, off);
    if ((tid & 31) == 0) red[tid >> 5] = sum;
    __syncthreads();
    if (tid < 8) {
        float x = red[tid];
#pragma unroll
        for (int off = 4; off > 0; off >>= 1) x += __shfl_xor_sync(0xffu, x, off);
        if (tid == 0) red[0] = x;
    }
    __syncthreads();
    const float mean = red[0] / DOUT;
    __syncthreads();
    float vs = 0.f;
#pragma unroll
    for (int t = 0; t < 3; t++) { float d = v[t] - mean; vs += d * d; }
#pragma unroll
    for (int off = 16; off > 0; off >>= 1) vs += __shfl_xor_sync(0xffffffffu, vs, off);
    if ((tid & 31) == 0) red[tid >> 5] = vs;
    __syncthreads();
    if (tid < 8) {
        float x = red[tid];
#pragma unroll
        for (int off = 4; off > 0; off >>= 1) x += __shfl_xor_sync(0xffu, x, off);
        if (tid == 0) red[0] = x;
    }
    __syncthreads();
    const float rstd = rsqrtf(red[0] / DOUT + 1e-5f);
#pragma unroll
    for (int t = 0; t < 3; t++) {
        int c = tid + t * 256;
        out[(long)n * DOUT + c] = (v[t] - mean) * rstd * g[c] + b[c];
    }
}

// ---------------- host ----------------
extern "C" void kernel_launch(void* const* d_in, const int* in_sizes, int n_in,
                              void* d_out, int out_size)
{
    const float* X    = (const float*)d_in[0];
    const int*   adj  = (const int*)  d_in[1];
    const float* ew   = (const float*)d_in[2];
    const float* W0   = (const float*)d_in[3];
    const float* a0   = (const float*)d_in[4];
    const float* W1   = (const float*)d_in[5];
    const float* a1   = (const float*)d_in[6];
    const float* rp0w = (const float*)d_in[7];
    const float* rp0b = (const float*)d_in[8];
    const float* rp1w = (const float*)d_in[9];
    const float* rp1b = (const float*)d_in[10];
    const float* ln0g = (const float*)d_in[11];
    const float* ln0b = (const float*)d_in[12];
    const float* ln1g = (const float*)d_in[13];
    const float* ln1b = (const float*)d_in[14];
    float* out = (float*)d_out;

    __half *Xh, *W0T, *rp0T, *W1T, *rp1T, *Wh0T, *Wh1T, *P, *H1;
    float *ssrc, *sdst, *Hcat, *R, *HP1h;
    cudaGetSymbolAddress((void**)&Xh,   g_Xh);
    cudaGetSymbolAddress((void**)&W0T,  g_W0T);
    cudaGetSymbolAddress((void**)&rp0T, g_rp0T);
    cudaGetSymbolAddress((void**)&W1T,  g_W1T);
    cudaGetSymbolAddress((void**)&rp1T, g_rp1T);
    cudaGetSymbolAddress((void**)&Wh0T, g_Wh0T);
    cudaGetSymbolAddress((void**)&Wh1T, g_Wh1T);
    cudaGetSymbolAddress((void**)&P,    g_P);
    cudaGetSymbolAddress((void**)&H1,   g_H1);
    cudaGetSymbolAddress((void**)&ssrc, g_ssrc);
    cudaGetSymbolAddress((void**)&sdst, g_sdst);
    cudaGetSymbolAddress((void**)&Hcat, g_Hcat);
    cudaGetSymbolAddress((void**)&R,    g_R);
    cudaGetSymbolAddress((void**)&HP1h, g_HP1h);

    cudaFuncSetAttribute(hgemm_mma, cudaFuncAttributeMaxDynamicSharedMemorySize, GEMM_SMEM);

    dim3 blk(256);
    dim3 tb(32, 8);

    // ---- prep: fp16 convert + transposes ----
    { long n = (long)NN * DIN; conv_half<<<(unsigned)((n/4 + 255)/256), blk>>>(X, Xh, n); }
    transpose_h<<<dim3(HID/32, DIN/32, H), tb>>>(W0, W0T, DIN, HID);
    transpose_h<<<dim3(HCAT/32, DIN/32, 1), tb>>>(rp0w, rp0T, DIN, HCAT);
    transpose_h<<<dim3(DOUT/32, HCAT/32, H), tb>>>(W1, W1T, HCAT, DOUT);
    transpose_h<<<dim3(DOUT/32, HCAT/32, 1), tb>>>(rp1w, rp1T, HCAT, DOUT);

    // ===== Layer 0 =====
    // Wh0T[h] = (Xh @ W0[h])^T : M=4096 N=512 K=768, transposed fp16 out
    hgemm_mma<<<dim3(HID/BN, NN/BM, H), blk, GEMM_SMEM>>>(
        Xh, W0T, Wh0T, DIN, 0L, (long)HID * DIN, (long)HID * NN, NN,
        1.f, nullptr, 1);
    scores_kernel<<<dim3(NN/256, H), blk>>>(Wh0T, a0, ssrc, sdst, HID);
    attn_kernel<<<dim3(NN, H), blk>>>(adj, ew, ssrc, sdst, P);
    // Hcat[n][h*512+o] = P[h] @ Wh0[h] : N=512 K=4096, f32 store ldc=2048
    hgemm_mma<<<dim3(HID/BN, NN/BM, H), blk, GEMM_SMEM>>>(
        P, Wh0T, Hcat, NN, (long)NN * NN, (long)HID * NN, (long)HID, HCAT,
        1.f, nullptr, 0);
    // R = Xh @ rp0w + rp0b : N=2048 K=768
    hgemm_mma<<<dim3(HCAT/BN, NN/BM, 1), blk, GEMM_SMEM>>>(
        Xh, rp0T, R, DIN, 0L, 0L, 0L, HCAT,
        1.f, rp0b, 0);
    fuse0_kernel<<<NN, blk>>>(Hcat, R, ln0g, ln0b, H1);

    // ===== Layer 1 =====
    // Wh1T[h] = (H1 @ W1[h])^T : N=768 K=2048, transposed fp16 out
    hgemm_mma<<<dim3(DOUT/BN, NN/BM, H), blk, GEMM_SMEM>>>(
        H1, W1T, Wh1T, HCAT, 0L, (long)DOUT * HCAT, (long)DOUT * NN, NN,
        1.f, nullptr, 1);
    scores_kernel<<<dim3(NN/256, H), blk>>>(Wh1T, a1, ssrc, sdst, DOUT);
    attn_kernel<<<dim3(NN, H), blk>>>(adj, ew, ssrc, sdst, P);
    // HP1h[h] = 0.25 * P[h] @ Wh1[h] : N=768 K=4096, f32 store
    hgemm_mma<<<dim3(DOUT/BN, NN/BM, H), blk, GEMM_SMEM>>>(
        P, Wh1T, HP1h, NN, (long)NN * NN, (long)DOUT * NN, (long)NN * DOUT, DOUT,
        0.25f, nullptr, 0);
    // R1 = H1 @ rp1w + rp1b : N=768 K=2048 (reuse R, ldc=DOUT)
    hgemm_mma<<<dim3(DOUT/BN, NN/BM, 1), blk, GEMM_SMEM>>>(
        H1, rp1T, R, HCAT, 0L, 0L, 0L, DOUT,
        1.f, rp1b, 0);
    final_kernel<<<NN, blk>>>(HP1h, R, ln1g, ln1b, out);
}